// round 2
// baseline (speedup 1.0000x reference)
#include <cuda_runtime.h>
#include <cuda_bf16.h>
#include <math.h>

#define T 2048
#define H 4096
#define NH 32
#define NKV 8
#define HD 128
#define QKVW ((NH + 2 * NKV) * HD)   /* 6144 */
#define SCALE 0.08838834764831845f   /* HD^-0.5 */

// ---------------- scratch (static device memory; no allocs allowed) ----------
__device__ float g_qkv[T * QKVW];       // 50.3 MB
__device__ float g_q[T * NH * HD];      // 33.5 MB (normed+roped+scaled)
__device__ float g_k[T * NKV * HD];     //  8.4 MB (normed+roped)
__device__ float g_attn[T * NH * HD];   // 33.5 MB

// ---------------- SGEMM: C[M,N] = A[M,K] @ B[K,N], all row-major -------------
// 128x128 block tile, BK=8, 256 threads, 8x8 microtile per thread.
__global__ __launch_bounds__(256) void sgemm_kernel(
    const float* __restrict__ A, const float* __restrict__ B,
    float* __restrict__ C, int M, int N, int K)
{
    __shared__ float As[8][128];   // stored transposed: As[k][m]
    __shared__ float Bs[8][128];   // Bs[k][n]

    int tid = threadIdx.x;
    int tx = tid & 15, ty = tid >> 4;
    int bm = blockIdx.y * 128;
    int bn = blockIdx.x * 128;

    float acc[8][8];
#pragma unroll
    for (int i = 0; i < 8; i++)
#pragma unroll
        for (int j = 0; j < 8; j++) acc[i][j] = 0.f;

    int arow = tid >> 1;          // 0..127
    int ak   = (tid & 1) * 4;     // 0 or 4
    int brow = tid >> 5;          // 0..7
    int bcol = (tid & 31) * 4;    // 0..124

    const float* Aptr = A + (size_t)(bm + arow) * K + ak;
    const float* Bptr = B + (size_t)brow * N + bn + bcol;

    for (int kt = 0; kt < K; kt += 8) {
        float4 a4 = *(const float4*)(Aptr + kt);
        As[ak + 0][arow] = a4.x;
        As[ak + 1][arow] = a4.y;
        As[ak + 2][arow] = a4.z;
        As[ak + 3][arow] = a4.w;
        float4 b4 = *(const float4*)(Bptr + (size_t)kt * N);
        *(float4*)&Bs[brow][bcol] = b4;
        __syncthreads();

#pragma unroll
        for (int kk = 0; kk < 8; kk++) {
            float a[8], b[8];
            *(float4*)(a)     = *(float4*)&As[kk][ty * 8];
            *(float4*)(a + 4) = *(float4*)&As[kk][ty * 8 + 4];
            *(float4*)(b)     = *(float4*)&Bs[kk][tx * 8];
            *(float4*)(b + 4) = *(float4*)&Bs[kk][tx * 8 + 4];
#pragma unroll
            for (int i = 0; i < 8; i++)
#pragma unroll
                for (int j = 0; j < 8; j++)
                    acc[i][j] += a[i] * b[j];
        }
        __syncthreads();
    }

#pragma unroll
    for (int i = 0; i < 8; i++) {
        float* Crow = C + (size_t)(bm + ty * 8 + i) * N + bn + tx * 8;
        *(float4*)Crow       = make_float4(acc[i][0], acc[i][1], acc[i][2], acc[i][3]);
        *(float4*)(Crow + 4) = make_float4(acc[i][4], acc[i][5], acc[i][6], acc[i][7]);
    }
}

// ---------------- per-(token, head) LayerNorm + interleaved RoPE -------------
// grid (T, NH+NKV); first NH y-blocks are Q heads, rest are K heads.
__global__ __launch_bounds__(128) void norm_rope_kernel(
    const int* __restrict__ positions,
    const float* __restrict__ qw, const float* __restrict__ kw)
{
    int t  = blockIdx.x;
    int hh = blockIdx.y;
    bool is_q = hh < NH;
    int head  = is_q ? hh : hh - NH;
    int base  = t * QKVW + (is_q ? head * HD : NH * HD + head * HD);
    int c = threadIdx.x;

    float x = g_qkv[base + c];

    __shared__ float red[4];
    __shared__ float ybuf[HD];

    float s = x;
#pragma unroll
    for (int o = 16; o; o >>= 1) s += __shfl_xor_sync(0xffffffffu, s, o);
    if ((c & 31) == 0) red[c >> 5] = s;
    __syncthreads();
    float mean = (red[0] + red[1] + red[2] + red[3]) * (1.0f / HD);
    __syncthreads();

    float d  = x - mean;
    float s2 = d * d;
#pragma unroll
    for (int o = 16; o; o >>= 1) s2 += __shfl_xor_sync(0xffffffffu, s2, o);
    if ((c & 31) == 0) red[c >> 5] = s2;
    __syncthreads();
    float var = (red[0] + red[1] + red[2] + red[3]) * (1.0f / HD);

    float w = is_q ? qw[head * HD + c] : kw[head * HD + c];
    ybuf[c] = d * rsqrtf(var + 1e-5f) * w;
    __syncthreads();

    if (c < HD / 2) {
        float x1 = ybuf[2 * c], x2 = ybuf[2 * c + 1];
        float fpos = (float)positions[t];
        // inv_freq = theta^(-2c/HD) = 2^(-(2c/HD) * log2(10000))
        float inv_freq = exp2f(-((float)(2 * c) * (1.0f / HD)) * 13.287712379549449f);
        float f = fpos * inv_freq;
        float sn, cs;
        sincosf(f, &sn, &cs);
        float o1 = x1 * cs - x2 * sn;
        float o2 = x2 * cs + x1 * sn;
        if (is_q) {
            float* dst = &g_q[t * (NH * HD) + head * HD];
            dst[2 * c]     = o1 * SCALE;   // pre-scale Q
            dst[2 * c + 1] = o2 * SCALE;
        } else {
            float* dst = &g_k[t * (NKV * HD) + head * HD];
            dst[2 * c]     = o1;
            dst[2 * c + 1] = o2;
        }
    }
}

// ---------------- causal flash attention, BM=BN=64, 256 threads --------------
// Shared: Qs[128][64] (transposed), KVs union (K:[128][64] / V:[64][132]),
//         Ps[64][68] (P transposed), m[64], l[64].
#define QS_ELEMS  (128 * 64)
#define KV_ELEMS  (64 * 132)      /* 8448 >= 8192 */
#define PS_ELEMS  (64 * 68)
#define FLASH_SMEM ((QS_ELEMS + KV_ELEMS + PS_ELEMS + 128) * 4)

__global__ __launch_bounds__(256) void flash_kernel()
{
    extern __shared__ float smf[];
    float* Qs   = smf;
    float* KVs  = Qs + QS_ELEMS;
    float* Ps   = KVs + KV_ELEMS;
    float* mrow = Ps + PS_ELEMS;
    float* lrow = mrow + 64;

    int qb  = blockIdx.x;       // q tile
    int h   = blockIdx.y;       // q head
    int hkv = h >> 2;           // GQA: NH/NKV = 4
    int tid = threadIdx.x;
    int tx = tid & 15, ty = tid >> 4;
    int r0 = ty * 4;            // S/O rows
    int j0 = tx * 4;            // S cols
    int c0 = tx * 8;            // O cols

    // load Q tile transposed (already scaled by HD^-0.5)
    for (int idx = tid; idx < 2048; idx += 256) {
        int r  = idx >> 5;
        int k4 = (idx & 31) << 2;
        float4 v = *(const float4*)&g_q[(qb * 64 + r) * (NH * HD) + h * HD + k4];
        Qs[(k4 + 0) * 64 + r] = v.x;
        Qs[(k4 + 1) * 64 + r] = v.y;
        Qs[(k4 + 2) * 64 + r] = v.z;
        Qs[(k4 + 3) * 64 + r] = v.w;
    }
    if (tid < 64) { mrow[tid] = -3.0e38f; lrow[tid] = 0.f; }

    float O[4][8];
#pragma unroll
    for (int i = 0; i < 4; i++)
#pragma unroll
        for (int c = 0; c < 8; c++) O[i][c] = 0.f;

    __syncthreads();

    for (int kb = 0; kb <= qb; kb++) {
        // ---- load K tile transposed: KVs[k][j] ----
        for (int idx = tid; idx < 2048; idx += 256) {
            int j  = idx >> 5;
            int k4 = (idx & 31) << 2;
            float4 v = *(const float4*)&g_k[(kb * 64 + j) * (NKV * HD) + hkv * HD + k4];
            KVs[(k4 + 0) * 64 + j] = v.x;
            KVs[(k4 + 1) * 64 + j] = v.y;
            KVs[(k4 + 2) * 64 + j] = v.z;
            KVs[(k4 + 3) * 64 + j] = v.w;
        }
        __syncthreads();

        // ---- S = Q @ K^T  (4x4 microtile) ----
        float S[4][4];
#pragma unroll
        for (int i = 0; i < 4; i++)
#pragma unroll
            for (int jj = 0; jj < 4; jj++) S[i][jj] = 0.f;

#pragma unroll 4
        for (int kk = 0; kk < 128; kk++) {
            float4 a = *(float4*)&Qs[kk * 64 + r0];
            float4 b = *(float4*)&KVs[kk * 64 + j0];
            float av[4] = {a.x, a.y, a.z, a.w};
            float bv[4] = {b.x, b.y, b.z, b.w};
#pragma unroll
            for (int i = 0; i < 4; i++)
#pragma unroll
                for (int jj = 0; jj < 4; jj++)
                    S[i][jj] += av[i] * bv[jj];
        }

        // ---- causal mask (only the diagonal tile needs it) ----
        if (kb == qb) {
#pragma unroll
            for (int i = 0; i < 4; i++)
#pragma unroll
                for (int jj = 0; jj < 4; jj++)
                    if (j0 + jj > r0 + i) S[i][jj] = -3.0e38f;
        }

        // ---- online softmax (row groups = 16 lanes sharing ty) ----
        float mold[4], mnew[4], alpha[4], lsum[4];
#pragma unroll
        for (int i = 0; i < 4; i++) {
            mold[i] = mrow[r0 + i];
            float mx = fmaxf(fmaxf(S[i][0], S[i][1]), fmaxf(S[i][2], S[i][3]));
#pragma unroll
            for (int o = 8; o; o >>= 1) mx = fmaxf(mx, __shfl_xor_sync(0xffffffffu, mx, o));
            mnew[i]  = fmaxf(mold[i], mx);
            alpha[i] = __expf(mold[i] - mnew[i]);
            float ls = 0.f;
#pragma unroll
            for (int jj = 0; jj < 4; jj++) {
                float p = __expf(S[i][jj] - mnew[i]);
                S[i][jj] = p;
                ls += p;
            }
#pragma unroll
            for (int o = 8; o; o >>= 1) ls += __shfl_xor_sync(0xffffffffu, ls, o);
            lsum[i] = ls;
        }
        __syncwarp();
        if (tx == 0) {
#pragma unroll
            for (int i = 0; i < 4; i++) {
                mrow[r0 + i] = mnew[i];
                lrow[r0 + i] = alpha[i] * lrow[r0 + i] + lsum[i];
            }
        }

        // ---- write P transposed: Ps[j][r] ----
#pragma unroll
        for (int jj = 0; jj < 4; jj++)
#pragma unroll
            for (int i = 0; i < 4; i++)
                Ps[(j0 + jj) * 68 + r0 + i] = S[i][jj];

        // ---- rescale O accumulators ----
#pragma unroll
        for (int i = 0; i < 4; i++)
#pragma unroll
            for (int c = 0; c < 8; c++) O[i][c] *= alpha[i];

        __syncthreads();   // K reads done + Ps written

        // ---- load V tile into KVs as [j][132] ----
        for (int idx = tid; idx < 2048; idx += 256) {
            int j  = idx >> 5;
            int c4 = (idx & 31) << 2;
            float4 v = *(const float4*)
                &g_qkv[(kb * 64 + j) * QKVW + (NH + NKV) * HD + hkv * HD + c4];
            *(float4*)&KVs[j * 132 + c4] = v;
        }
        __syncthreads();

        // ---- O += P @ V  (4x8 microtile) ----
#pragma unroll 2
        for (int j = 0; j < 64; j++) {
            float4 p  = *(float4*)&Ps[j * 68 + r0];
            float4 va = *(float4*)&KVs[j * 132 + c0];
            float4 vb = *(float4*)&KVs[j * 132 + c0 + 4];
            float pv[4] = {p.x, p.y, p.z, p.w};
            float vv[8] = {va.x, va.y, va.z, va.w, vb.x, vb.y, vb.z, vb.w};
#pragma unroll
            for (int i = 0; i < 4; i++)
#pragma unroll
                for (int c = 0; c < 8; c++)
                    O[i][c] += pv[i] * vv[c];
        }
        __syncthreads();   // before next iter overwrites KVs/Ps
    }

    // ---- epilogue: normalize and store ----
#pragma unroll
    for (int i = 0; i < 4; i++) {
        float inv = 1.0f / lrow[r0 + i];
        float* op = &g_attn[(qb * 64 + r0 + i) * (NH * HD) + h * HD + c0];
        *(float4*)op       = make_float4(O[i][0] * inv, O[i][1] * inv,
                                         O[i][2] * inv, O[i][3] * inv);
        *(float4*)(op + 4) = make_float4(O[i][4] * inv, O[i][5] * inv,
                                         O[i][6] * inv, O[i][7] * inv);
    }
}

// ---------------- launch ----------------
extern "C" void kernel_launch(void* const* d_in, const int* in_sizes, int n_in,
                              void* d_out, int out_size)
{
    const int*   positions = (const int*)d_in[0];
    const float* hidden    = (const float*)d_in[1];
    const float* w_qkv     = (const float*)d_in[2];
    const float* w_o       = (const float*)d_in[3];
    const float* qw        = (const float*)d_in[4];
    const float* kw        = (const float*)d_in[5];
    float*       out       = (float*)d_out;

    float *qkvp, *attnp;
    cudaGetSymbolAddress((void**)&qkvp,  g_qkv);
    cudaGetSymbolAddress((void**)&attnp, g_attn);

    cudaFuncSetAttribute(flash_kernel,
                         cudaFuncAttributeMaxDynamicSharedMemorySize, FLASH_SMEM);

    // 1) QKV projection: [T,H] @ [H,QKVW]
    sgemm_kernel<<<dim3(QKVW / 128, T / 128), 256>>>(hidden, w_qkv, qkvp, T, QKVW, H);

    // 2) per-head LayerNorm + RoPE (+ Q scaling), V stays in g_qkv
    norm_rope_kernel<<<dim3(T, NH + NKV), 128>>>(positions, qw, kw);

    // 3) causal flash attention
    flash_kernel<<<dim3(T / 64, NH), 256, FLASH_SMEM>>>();

    // 4) output projection: [T, NH*HD] @ [NH*HD, H]
    sgemm_kernel<<<dim3(H / 128, T / 128), 256>>>(attnp, w_o, out, T, H, NH * HD);
}

// round 4
// speedup vs baseline: 1.4882x; 1.4882x over previous
#include <cuda_runtime.h>
#include <cuda_bf16.h>
#include <math.h>
#include <stdint.h>

#define T 2048
#define H 4096
#define NH 32
#define NKV 8
#define HD 128
#define QKVW ((NH + 2 * NKV) * HD)   /* 6144 */
#define SCALE 0.08838834764831845f   /* HD^-0.5 */

// ---------------- scratch (static device memory; no allocs allowed) ----------
__device__ float g_qkv[T * QKVW];       // 50.3 MB
__device__ float g_q[T * NH * HD];      // 33.5 MB (normed+roped+scaled)
__device__ float g_k[T * NKV * HD];     //  8.4 MB (normed+roped)
__device__ float g_attn[T * NH * HD];   // 33.5 MB

// ================= TF32 tensor-core GEMM (3xTF32 hi/lo split) ================
// C[M,N] = A[M,K] @ B[K,N], row-major. BM=BN=128, BK=16, 256 threads,
// 8 warps in 2x4, warp tile 64x32, mma.sync m16n8k8 tf32.
// Precision: a = ah + al (ah = a masked to tf32); product uses
// ah*bh + ah*bl + al*bh  (error ~2^-20 relative, i.e. fp32-class).

__device__ __forceinline__ void mma_tf32(float c[4],
    uint32_t a0, uint32_t a1, uint32_t a2, uint32_t a3,
    uint32_t b0, uint32_t b1)
{
    asm volatile(
        "mma.sync.aligned.m16n8k8.row.col.f32.tf32.tf32.f32 "
        "{%0,%1,%2,%3},{%4,%5,%6,%7},{%8,%9},{%0,%1,%2,%3};\n"
        : "+f"(c[0]), "+f"(c[1]), "+f"(c[2]), "+f"(c[3])
        : "r"(a0), "r"(a1), "r"(a2), "r"(a3), "r"(b0), "r"(b1));
}

__device__ __forceinline__ void split_tf32(float x, uint32_t& hi, uint32_t& lo)
{
    float h = __uint_as_float(__float_as_uint(x) & 0xffffe000u);
    hi = __float_as_uint(h);
    lo = __float_as_uint(x - h);   // exact in fp32
}

#define SM_STRIDE 136   /* floats per k-row; 136%32==8 -> conflict-free frags */

__global__ __launch_bounds__(256) void gemm_tf32_kernel(
    const float* __restrict__ A, const float* __restrict__ B,
    float* __restrict__ C, int M, int N, int K)
{
    __shared__ float As[16 * SM_STRIDE];   // As[k][m]
    __shared__ float Bs[16 * SM_STRIDE];   // Bs[k][n]

    int tid  = threadIdx.x;
    int warp = tid >> 5, lane = tid & 31;
    int gid  = lane >> 2, t4 = lane & 3;
    int wm   = (warp >> 2) * 64;           // warp row offset (2 rows of warps)
    int wn   = (warp & 3) * 32;            // warp col offset (4 cols of warps)
    int bm   = blockIdx.y * 128;
    int bn   = blockIdx.x * 128;

    float acc[4][4][4];
#pragma unroll
    for (int mi = 0; mi < 4; mi++)
#pragma unroll
        for (int ni = 0; ni < 4; ni++)
#pragma unroll
            for (int r = 0; r < 4; r++) acc[mi][ni][r] = 0.f;

    // gmem load assignments
    int a_row = tid >> 1;            // 0..127
    int a_col = (tid & 1) * 8;       // 0 or 8
    int b_row = tid >> 5;            // 0..7 (and +8)
    int b_col = (tid & 31) * 4;      // 0..124

    const float* Aptr = A + (size_t)(bm + a_row) * K + a_col;
    const float* Bptr = B + (size_t)b_row * N + bn + b_col;

    float4 pa0, pa1, pb0, pb1;
    pa0 = *(const float4*)(Aptr + 0);
    pa1 = *(const float4*)(Aptr + 4);
    pb0 = *(const float4*)(Bptr);
    pb1 = *(const float4*)(Bptr + (size_t)8 * N);

    for (int kt = 0; kt < K; kt += 16) {
        // ---- stage to shared ----
        {
            float a0v[4] = {pa0.x, pa0.y, pa0.z, pa0.w};
            float a1v[4] = {pa1.x, pa1.y, pa1.z, pa1.w};
#pragma unroll
            for (int j = 0; j < 4; j++) {
                As[(a_col + j) * SM_STRIDE + a_row]     = a0v[j];
                As[(a_col + 4 + j) * SM_STRIDE + a_row] = a1v[j];
            }
            *(float4*)&Bs[b_row * SM_STRIDE + b_col]       = pb0;
            *(float4*)&Bs[(b_row + 8) * SM_STRIDE + b_col] = pb1;
        }
        __syncthreads();

        // ---- prefetch next tile ----
        if (kt + 16 < K) {
            pa0 = *(const float4*)(Aptr + kt + 16);
            pa1 = *(const float4*)(Aptr + kt + 20);
            pb0 = *(const float4*)(Bptr + (size_t)(kt + 16) * N);
            pb1 = *(const float4*)(Bptr + (size_t)(kt + 24) * N);
        }

        // ---- compute: 2 k-chunks of 8 ----
#pragma unroll
        for (int kc = 0; kc < 16; kc += 8) {
            uint32_t ah[4][4], al[4][4];
#pragma unroll
            for (int mi = 0; mi < 4; mi++) {
                int m = wm + mi * 16 + gid;
                float x0 = As[(kc + t4) * SM_STRIDE + m];
                float x1 = As[(kc + t4) * SM_STRIDE + m + 8];
                float x2 = As[(kc + t4 + 4) * SM_STRIDE + m];
                float x3 = As[(kc + t4 + 4) * SM_STRIDE + m + 8];
                split_tf32(x0, ah[mi][0], al[mi][0]);
                split_tf32(x1, ah[mi][1], al[mi][1]);
                split_tf32(x2, ah[mi][2], al[mi][2]);
                split_tf32(x3, ah[mi][3], al[mi][3]);
            }
            uint32_t bh[4][2], bl[4][2];
#pragma unroll
            for (int ni = 0; ni < 4; ni++) {
                int n = wn + ni * 8 + gid;
                float y0 = Bs[(kc + t4) * SM_STRIDE + n];
                float y1 = Bs[(kc + t4 + 4) * SM_STRIDE + n];
                split_tf32(y0, bh[ni][0], bl[ni][0]);
                split_tf32(y1, bh[ni][1], bl[ni][1]);
            }
#pragma unroll
            for (int mi = 0; mi < 4; mi++)
#pragma unroll
                for (int ni = 0; ni < 4; ni++) {
                    mma_tf32(acc[mi][ni], ah[mi][0], ah[mi][1], ah[mi][2], ah[mi][3],
                             bh[ni][0], bh[ni][1]);
                    mma_tf32(acc[mi][ni], ah[mi][0], ah[mi][1], ah[mi][2], ah[mi][3],
                             bl[ni][0], bl[ni][1]);
                    mma_tf32(acc[mi][ni], al[mi][0], al[mi][1], al[mi][2], al[mi][3],
                             bh[ni][0], bh[ni][1]);
                }
        }
        __syncthreads();
    }

    // ---- epilogue ----
#pragma unroll
    for (int mi = 0; mi < 4; mi++)
#pragma unroll
        for (int ni = 0; ni < 4; ni++) {
            int row = bm + wm + mi * 16 + gid;
            int col = bn + wn + ni * 8 + t4 * 2;
            *(float2*)&C[(size_t)row * N + col] =
                make_float2(acc[mi][ni][0], acc[mi][ni][1]);
            *(float2*)&C[(size_t)(row + 8) * N + col] =
                make_float2(acc[mi][ni][2], acc[mi][ni][3]);
        }
}

// ---------------- per-(token, head) LayerNorm + interleaved RoPE -------------
__global__ __launch_bounds__(128) void norm_rope_kernel(
    const int* __restrict__ positions,
    const float* __restrict__ qw, const float* __restrict__ kw)
{
    int t  = blockIdx.x;
    int hh = blockIdx.y;
    bool is_q = hh < NH;
    int head  = is_q ? hh : hh - NH;
    int base  = t * QKVW + (is_q ? head * HD : NH * HD + head * HD);
    int c = threadIdx.x;

    float x = g_qkv[base + c];

    __shared__ float red[4];
    __shared__ float ybuf[HD];

    float s = x;
#pragma unroll
    for (int o = 16; o; o >>= 1) s += __shfl_xor_sync(0xffffffffu, s, o);
    if ((c & 31) == 0) red[c >> 5] = s;
    __syncthreads();
    float mean = (red[0] + red[1] + red[2] + red[3]) * (1.0f / HD);
    __syncthreads();

    float d  = x - mean;
    float s2 = d * d;
#pragma unroll
    for (int o = 16; o; o >>= 1) s2 += __shfl_xor_sync(0xffffffffu, s2, o);
    if ((c & 31) == 0) red[c >> 5] = s2;
    __syncthreads();
    float var = (red[0] + red[1] + red[2] + red[3]) * (1.0f / HD);

    float w = is_q ? qw[head * HD + c] : kw[head * HD + c];
    ybuf[c] = d * rsqrtf(var + 1e-5f) * w;
    __syncthreads();

    if (c < HD / 2) {
        float x1 = ybuf[2 * c], x2 = ybuf[2 * c + 1];
        float fpos = (float)positions[t];
        float inv_freq = exp2f(-((float)(2 * c) * (1.0f / HD)) * 13.287712379549449f);
        float f = fpos * inv_freq;
        float sn, cs;
        sincosf(f, &sn, &cs);
        float o1 = x1 * cs - x2 * sn;
        float o2 = x2 * cs + x1 * sn;
        if (is_q) {
            float* dst = &g_q[t * (NH * HD) + head * HD];
            dst[2 * c]     = o1 * SCALE;
            dst[2 * c + 1] = o2 * SCALE;
        } else {
            float* dst = &g_k[t * (NKV * HD) + head * HD];
            dst[2 * c]     = o1;
            dst[2 * c + 1] = o2;
        }
    }
}

// ---------------- causal flash attention, BM=BN=64, 256 threads --------------
#define QS_ELEMS  (128 * 64)
#define KV_ELEMS  (64 * 132)
#define PS_ELEMS  (64 * 68)
#define FLASH_SMEM ((QS_ELEMS + KV_ELEMS + PS_ELEMS + 128) * 4)

__global__ __launch_bounds__(256) void flash_kernel()
{
    extern __shared__ float smf[];
    float* Qs   = smf;
    float* KVs  = Qs + QS_ELEMS;
    float* Ps   = KVs + KV_ELEMS;
    float* mrow = Ps + PS_ELEMS;
    float* lrow = mrow + 64;

    int qb  = blockIdx.x;
    int h   = blockIdx.y;
    int hkv = h >> 2;
    int tid = threadIdx.x;
    int tx = tid & 15, ty = tid >> 4;
    int r0 = ty * 4;
    int j0 = tx * 4;
    int c0 = tx * 8;

    for (int idx = tid; idx < 2048; idx += 256) {
        int r  = idx >> 5;
        int k4 = (idx & 31) << 2;
        float4 v = *(const float4*)&g_q[(qb * 64 + r) * (NH * HD) + h * HD + k4];
        Qs[(k4 + 0) * 64 + r] = v.x;
        Qs[(k4 + 1) * 64 + r] = v.y;
        Qs[(k4 + 2) * 64 + r] = v.z;
        Qs[(k4 + 3) * 64 + r] = v.w;
    }
    if (tid < 64) { mrow[tid] = -3.0e38f; lrow[tid] = 0.f; }

    float O[4][8];
#pragma unroll
    for (int i = 0; i < 4; i++)
#pragma unroll
        for (int c = 0; c < 8; c++) O[i][c] = 0.f;

    __syncthreads();

    for (int kb = 0; kb <= qb; kb++) {
        for (int idx = tid; idx < 2048; idx += 256) {
            int j  = idx >> 5;
            int k4 = (idx & 31) << 2;
            float4 v = *(const float4*)&g_k[(kb * 64 + j) * (NKV * HD) + hkv * HD + k4];
            KVs[(k4 + 0) * 64 + j] = v.x;
            KVs[(k4 + 1) * 64 + j] = v.y;
            KVs[(k4 + 2) * 64 + j] = v.z;
            KVs[(k4 + 3) * 64 + j] = v.w;
        }
        __syncthreads();

        float S[4][4];
#pragma unroll
        for (int i = 0; i < 4; i++)
#pragma unroll
            for (int jj = 0; jj < 4; jj++) S[i][jj] = 0.f;

#pragma unroll 4
        for (int kk = 0; kk < 128; kk++) {
            float4 a = *(float4*)&Qs[kk * 64 + r0];
            float4 b = *(float4*)&KVs[kk * 64 + j0];
            float av[4] = {a.x, a.y, a.z, a.w};
            float bv[4] = {b.x, b.y, b.z, b.w};
#pragma unroll
            for (int i = 0; i < 4; i++)
#pragma unroll
                for (int jj = 0; jj < 4; jj++)
                    S[i][jj] += av[i] * bv[jj];
        }

        if (kb == qb) {
#pragma unroll
            for (int i = 0; i < 4; i++)
#pragma unroll
                for (int jj = 0; jj < 4; jj++)
                    if (j0 + jj > r0 + i) S[i][jj] = -3.0e38f;
        }

        float mold[4], mnew[4], alpha[4], lsum[4];
#pragma unroll
        for (int i = 0; i < 4; i++) {
            mold[i] = mrow[r0 + i];
            float mx = fmaxf(fmaxf(S[i][0], S[i][1]), fmaxf(S[i][2], S[i][3]));
#pragma unroll
            for (int o = 8; o; o >>= 1) mx = fmaxf(mx, __shfl_xor_sync(0xffffffffu, mx, o));
            mnew[i]  = fmaxf(mold[i], mx);
            alpha[i] = __expf(mold[i] - mnew[i]);
            float ls = 0.f;
#pragma unroll
            for (int jj = 0; jj < 4; jj++) {
                float p = __expf(S[i][jj] - mnew[i]);
                S[i][jj] = p;
                ls += p;
            }
#pragma unroll
            for (int o = 8; o; o >>= 1) ls += __shfl_xor_sync(0xffffffffu, ls, o);
            lsum[i] = ls;
        }
        __syncwarp();
        if (tx == 0) {
#pragma unroll
            for (int i = 0; i < 4; i++) {
                mrow[r0 + i] = mnew[i];
                lrow[r0 + i] = alpha[i] * lrow[r0 + i] + lsum[i];
            }
        }

#pragma unroll
        for (int jj = 0; jj < 4; jj++)
#pragma unroll
            for (int i = 0; i < 4; i++)
                Ps[(j0 + jj) * 68 + r0 + i] = S[i][jj];

#pragma unroll
        for (int i = 0; i < 4; i++)
#pragma unroll
            for (int c = 0; c < 8; c++) O[i][c] *= alpha[i];

        __syncthreads();

        for (int idx = tid; idx < 2048; idx += 256) {
            int j  = idx >> 5;
            int c4 = (idx & 31) << 2;
            float4 v = *(const float4*)
                &g_qkv[(kb * 64 + j) * QKVW + (NH + NKV) * HD + hkv * HD + c4];
            *(float4*)&KVs[j * 132 + c4] = v;
        }
        __syncthreads();

#pragma unroll 2
        for (int j = 0; j < 64; j++) {
            float4 p  = *(float4*)&Ps[j * 68 + r0];
            float4 va = *(float4*)&KVs[j * 132 + c0];
            float4 vb = *(float4*)&KVs[j * 132 + c0 + 4];
            float pv[4] = {p.x, p.y, p.z, p.w};
            float vv[8] = {va.x, va.y, va.z, va.w, vb.x, vb.y, vb.z, vb.w};
#pragma unroll
            for (int i = 0; i < 4; i++)
#pragma unroll
                for (int c = 0; c < 8; c++)
                    O[i][c] += pv[i] * vv[c];
        }
        __syncthreads();
    }

#pragma unroll
    for (int i = 0; i < 4; i++) {
        float inv = 1.0f / lrow[r0 + i];
        float* op = &g_attn[(qb * 64 + r0 + i) * (NH * HD) + h * HD + c0];
        *(float4*)op       = make_float4(O[i][0] * inv, O[i][1] * inv,
                                         O[i][2] * inv, O[i][3] * inv);
        *(float4*)(op + 4) = make_float4(O[i][4] * inv, O[i][5] * inv,
                                         O[i][6] * inv, O[i][7] * inv);
    }
}

// ---------------- launch ----------------
extern "C" void kernel_launch(void* const* d_in, const int* in_sizes, int n_in,
                              void* d_out, int out_size)
{
    const int*   positions = (const int*)d_in[0];
    const float* hidden    = (const float*)d_in[1];
    const float* w_qkv     = (const float*)d_in[2];
    const float* w_o       = (const float*)d_in[3];
    const float* qw        = (const float*)d_in[4];
    const float* kw        = (const float*)d_in[5];
    float*       out       = (float*)d_out;

    float *qkvp, *attnp;
    cudaGetSymbolAddress((void**)&qkvp,  g_qkv);
    cudaGetSymbolAddress((void**)&attnp, g_attn);

    cudaFuncSetAttribute(flash_kernel,
                         cudaFuncAttributeMaxDynamicSharedMemorySize, FLASH_SMEM);

    // 1) QKV projection: [T,H] @ [H,QKVW]  (tensor cores, 3xTF32)
    gemm_tf32_kernel<<<dim3(QKVW / 128, T / 128), 256>>>(hidden, w_qkv, qkvp, T, QKVW, H);

    // 2) per-head LayerNorm + RoPE (+ Q scaling), V stays in g_qkv
    norm_rope_kernel<<<dim3(T, NH + NKV), 128>>>(positions, qw, kw);

    // 3) causal flash attention
    flash_kernel<<<dim3(T / 64, NH), 256, FLASH_SMEM>>>();

    // 4) output projection: [T, NH*HD] @ [NH*HD, H]  (tensor cores, 3xTF32)
    gemm_tf32_kernel<<<dim3(H / 128, T / 128), 256>>>(attnp, w_o, out, T, H, NH * HD);
}

// round 6
// speedup vs baseline: 1.7715x; 1.1903x over previous
#include <cuda_runtime.h>
#include <cuda_bf16.h>
#include <math.h>
#include <stdint.h>

#define T 2048
#define H 4096
#define NH 32
#define NKV 8
#define HD 128
#define QKVW ((NH + 2 * NKV) * HD)   /* 6144 */
#define SCALE 0.08838834764831845f   /* HD^-0.5 */

// ---------------- scratch (static device memory; no allocs allowed) ----------
__device__ float g_qkv[T * QKVW];       // 50.3 MB
__device__ float g_q[T * NH * HD];      // 33.5 MB (normed+roped+scaled)
__device__ float g_k[T * NKV * HD];     //  8.4 MB (normed+roped)
__device__ float g_attn[T * NH * HD];   // 33.5 MB

// ================= common mma helpers ================
__device__ __forceinline__ void mma_tf32(float c[4],
    uint32_t a0, uint32_t a1, uint32_t a2, uint32_t a3,
    uint32_t b0, uint32_t b1)
{
    asm volatile(
        "mma.sync.aligned.m16n8k8.row.col.f32.tf32.tf32.f32 "
        "{%0,%1,%2,%3},{%4,%5,%6,%7},{%8,%9},{%0,%1,%2,%3};\n"
        : "+f"(c[0]), "+f"(c[1]), "+f"(c[2]), "+f"(c[3])
        : "r"(a0), "r"(a1), "r"(a2), "r"(a3), "r"(b0), "r"(b1));
}

__device__ __forceinline__ void split_tf32(float x, uint32_t& hi, uint32_t& lo)
{
    float h = __uint_as_float(__float_as_uint(x) & 0xffffe000u);
    hi = __float_as_uint(h);
    lo = __float_as_uint(x - h);   // exact in fp32
}

__device__ __forceinline__ void cp_async16(uint32_t dst, const void* src)
{
    asm volatile("cp.async.cg.shared.global [%0], [%1], 16;\n"
                 :: "r"(dst), "l"(src));
}

// ================= TF32 GEMM, cp.async 2-stage, BK=32 ================
// C[M,N] = A[M,K] @ B[K,N] row-major. BM=BN=128, 256 threads,
// warp tile 64x32, 3xTF32 hi/lo split.
#define AS_STRIDE 36               /* As[m][k] : (36*gid+t4)%32 = 4*gid+t4 -> cf */
#define BS_STRIDE 136              /* Bs[k][n] : (136*t4+gid)%32 = 8*t4+gid -> cf */
#define AS_SIZE (128 * AS_STRIDE)  /* 4608 floats */
#define BS_SIZE (32 * BS_STRIDE)   /* 4352 floats */
#define G_STAGE (AS_SIZE + BS_SIZE)
#define GEMM_SMEM (2 * G_STAGE * 4)   /* 71680 B */

__global__ __launch_bounds__(256) void gemm_tf32_async(
    const float* __restrict__ A, const float* __restrict__ B,
    float* __restrict__ C, int M, int N, int K)
{
    extern __shared__ float smg[];

    int tid  = threadIdx.x;
    int warp = tid >> 5, lane = tid & 31;
    int gid  = lane >> 2, t4 = lane & 3;
    int wm   = (warp >> 2) * 64;
    int wn   = (warp & 3) * 32;
    int bm   = blockIdx.y * 128;
    int bn   = blockIdx.x * 128;

    float acc[4][4][4];
#pragma unroll
    for (int mi = 0; mi < 4; mi++)
#pragma unroll
        for (int ni = 0; ni < 4; ni++)
#pragma unroll
            for (int r = 0; r < 4; r++) acc[mi][ni][r] = 0.f;

    uint32_t smbase = (uint32_t)__cvta_generic_to_shared(smg);
    int ar_base = tid >> 3;          // + 32*i
    int ac      = (tid & 7) * 4;
    int br_base = tid >> 5;          // + 8*i
    int bc      = (tid & 31) * 4;

    int niter = K >> 5;

    // prologue: stage 0
    {
#pragma unroll
        for (int i = 0; i < 4; i++) {
            int ar = ar_base + 32 * i;
            cp_async16(smbase + (ar * AS_STRIDE + ac) * 4,
                       A + (size_t)(bm + ar) * K + ac);
        }
#pragma unroll
        for (int i = 0; i < 4; i++) {
            int br = br_base + 8 * i;
            cp_async16(smbase + (AS_SIZE + br * BS_STRIDE + bc) * 4,
                       B + (size_t)br * N + bn + bc);
        }
        asm volatile("cp.async.commit_group;\n");
    }

    for (int it = 0; it < niter; it++) {
        int s = it & 1;
        if (it + 1 < niter) {
            int kt = (it + 1) << 5;
            uint32_t sb = smbase + (s ^ 1) * G_STAGE * 4;
#pragma unroll
            for (int i = 0; i < 4; i++) {
                int ar = ar_base + 32 * i;
                cp_async16(sb + (ar * AS_STRIDE + ac) * 4,
                           A + (size_t)(bm + ar) * K + kt + ac);
            }
#pragma unroll
            for (int i = 0; i < 4; i++) {
                int br = br_base + 8 * i;
                cp_async16(sb + (AS_SIZE + br * BS_STRIDE + bc) * 4,
                           B + (size_t)(kt + br) * N + bn + bc);
            }
            asm volatile("cp.async.commit_group;\n");
            asm volatile("cp.async.wait_group 1;\n");
        } else {
            asm volatile("cp.async.wait_group 0;\n");
        }
        __syncthreads();

        const float* As = smg + s * G_STAGE;
        const float* Bs = As + AS_SIZE;

#pragma unroll
        for (int kc = 0; kc < 32; kc += 8) {
            uint32_t ah[4][4], al[4][4];
#pragma unroll
            for (int mi = 0; mi < 4; mi++) {
                int m = wm + mi * 16 + gid;
                float x0 = As[m * AS_STRIDE + kc + t4];
                float x1 = As[(m + 8) * AS_STRIDE + kc + t4];
                float x2 = As[m * AS_STRIDE + kc + t4 + 4];
                float x3 = As[(m + 8) * AS_STRIDE + kc + t4 + 4];
                split_tf32(x0, ah[mi][0], al[mi][0]);
                split_tf32(x1, ah[mi][1], al[mi][1]);
                split_tf32(x2, ah[mi][2], al[mi][2]);
                split_tf32(x3, ah[mi][3], al[mi][3]);
            }
            uint32_t bh[4][2], bl[4][2];
#pragma unroll
            for (int ni = 0; ni < 4; ni++) {
                int n = wn + ni * 8 + gid;
                float y0 = Bs[(kc + t4) * BS_STRIDE + n];
                float y1 = Bs[(kc + t4 + 4) * BS_STRIDE + n];
                split_tf32(y0, bh[ni][0], bl[ni][0]);
                split_tf32(y1, bh[ni][1], bl[ni][1]);
            }
#pragma unroll
            for (int mi = 0; mi < 4; mi++)
#pragma unroll
                for (int ni = 0; ni < 4; ni++) {
                    mma_tf32(acc[mi][ni], ah[mi][0], ah[mi][1], ah[mi][2], ah[mi][3],
                             bh[ni][0], bh[ni][1]);
                    mma_tf32(acc[mi][ni], ah[mi][0], ah[mi][1], ah[mi][2], ah[mi][3],
                             bl[ni][0], bl[ni][1]);
                    mma_tf32(acc[mi][ni], al[mi][0], al[mi][1], al[mi][2], al[mi][3],
                             bh[ni][0], bh[ni][1]);
                }
        }
        __syncthreads();
    }

#pragma unroll
    for (int mi = 0; mi < 4; mi++)
#pragma unroll
        for (int ni = 0; ni < 4; ni++) {
            int row = bm + wm + mi * 16 + gid;
            int col = bn + wn + ni * 8 + t4 * 2;
            *(float2*)&C[(size_t)row * N + col] =
                make_float2(acc[mi][ni][0], acc[mi][ni][1]);
            *(float2*)&C[(size_t)(row + 8) * N + col] =
                make_float2(acc[mi][ni][2], acc[mi][ni][3]);
        }
}

// ---------------- per-(token, head) LayerNorm + interleaved RoPE -------------
__global__ __launch_bounds__(128) void norm_rope_kernel(
    const int* __restrict__ positions,
    const float* __restrict__ qw, const float* __restrict__ kw)
{
    int t  = blockIdx.x;
    int hh = blockIdx.y;
    bool is_q = hh < NH;
    int head  = is_q ? hh : hh - NH;
    int base  = t * QKVW + (is_q ? head * HD : NH * HD + head * HD);
    int c = threadIdx.x;

    float x = g_qkv[base + c];

    __shared__ float red[4];
    __shared__ float ybuf[HD];

    float s = x;
#pragma unroll
    for (int o = 16; o; o >>= 1) s += __shfl_xor_sync(0xffffffffu, s, o);
    if ((c & 31) == 0) red[c >> 5] = s;
    __syncthreads();
    float mean = (red[0] + red[1] + red[2] + red[3]) * (1.0f / HD);
    __syncthreads();

    float d  = x - mean;
    float s2 = d * d;
#pragma unroll
    for (int o = 16; o; o >>= 1) s2 += __shfl_xor_sync(0xffffffffu, s2, o);
    if ((c & 31) == 0) red[c >> 5] = s2;
    __syncthreads();
    float var = (red[0] + red[1] + red[2] + red[3]) * (1.0f / HD);

    float w = is_q ? qw[head * HD + c] : kw[head * HD + c];
    ybuf[c] = d * rsqrtf(var + 1e-5f) * w;
    __syncthreads();

    if (c < HD / 2) {
        float x1 = ybuf[2 * c], x2 = ybuf[2 * c + 1];
        float fpos = (float)positions[t];
        float inv_freq = exp2f(-((float)(2 * c) * (1.0f / HD)) * 13.287712379549449f);
        float f = fpos * inv_freq;
        float sn, cs;
        sincosf(f, &sn, &cs);
        float o1 = x1 * cs - x2 * sn;
        float o2 = x2 * cs + x1 * sn;
        if (is_q) {
            float* dst = &g_q[t * (NH * HD) + head * HD];
            dst[2 * c]     = o1 * SCALE;
            dst[2 * c + 1] = o2 * SCALE;
        } else {
            float* dst = &g_k[t * (NKV * HD) + head * HD];
            dst[2 * c]     = o1;
            dst[2 * c + 1] = o2;
        }
    }
}

// ================= tensor-core flash attention =================
// BM=128 rows of Q per block, BN=64 kv per iter, 256 thr = 8 warps.
// Each warp owns 16 Q rows -> softmax state entirely in registers.
// 3xTF32 split for both S=Q@K^T and O+=P@V.
#define QS_STRIDE 132   /* Qs[r][d]: (132*gid+t4)%32 = 4g+t4 cf */
#define KS_STRIDE 132   /* Ks[j][d]: same pattern */
#define VT_STRIDE 68    /* Vt[d][j]: (68*gid+t4)%32 = 4g+t4 cf */
#define PS_STRIDE 68    /* Ps[r][j] */
#define QS_SZ (128 * QS_STRIDE)
#define KS_SZ (64 * KS_STRIDE)
#define VT_SZ (128 * VT_STRIDE)
#define PS_SZ (128 * PS_STRIDE)
#define FLASH_SMEM ((QS_SZ + KS_SZ + VT_SZ + PS_SZ) * 4)   /* 171008 B */

__global__ __launch_bounds__(256) void flash_mma_kernel()
{
    extern __shared__ float smf[];
    float* Qs = smf;
    float* Ks = Qs + QS_SZ;
    float* Vt = Ks + KS_SZ;
    float* Ps = Vt + VT_SZ;

    int qb  = (gridDim.x - 1) - blockIdx.x;   // heavy blocks first
    int h   = blockIdx.y;
    int hkv = h >> 2;
    int tid = threadIdx.x;
    int w   = tid >> 5, lane = tid & 31;
    int gid = lane >> 2, t4 = lane & 3;
    int r0  = w * 16;                         // warp's local row base

    // ---- load Q tile [128][128] natural layout ----
    for (int idx = tid; idx < 128 * 32; idx += 256) {
        int r = idx >> 5, c4 = (idx & 31) << 2;
        float4 v = *(const float4*)&g_q[(qb * 128 + r) * (NH * HD) + h * HD + c4];
        *(float4*)&Qs[r * QS_STRIDE + c4] = v;
    }

    float of[16][4];
#pragma unroll
    for (int ni = 0; ni < 16; ni++)
#pragma unroll
        for (int r = 0; r < 4; r++) of[ni][r] = 0.f;
    float mst0 = -1e30f, mst1 = -1e30f, lst0 = 0.f, lst1 = 0.f;

    int nkb = 2 * qb + 2;
    for (int kb = 0; kb < nkb; kb++) {
        __syncthreads();   // prev iter's P/V reads done; Q visible (iter 0)

        // ---- K tile natural [j][d] ----
        for (int idx = tid; idx < 64 * 32; idx += 256) {
            int j = idx >> 5, c4 = (idx & 31) << 2;
            float4 v = *(const float4*)&g_k[(kb * 64 + j) * (NKV * HD) + hkv * HD + c4];
            *(float4*)&Ks[j * KS_STRIDE + c4] = v;
        }
        // ---- V tile transposed [d][j] ----
        for (int idx = tid; idx < 64 * 32; idx += 256) {
            int j = idx >> 5, c4 = (idx & 31) << 2;
            float4 v = *(const float4*)
                &g_qkv[(kb * 64 + j) * QKVW + (NH + NKV) * HD + hkv * HD + c4];
            Vt[(c4 + 0) * VT_STRIDE + j] = v.x;
            Vt[(c4 + 1) * VT_STRIDE + j] = v.y;
            Vt[(c4 + 2) * VT_STRIDE + j] = v.z;
            Vt[(c4 + 3) * VT_STRIDE + j] = v.w;
        }
        __syncthreads();

        // ---- S = Q @ K^T : 8 n-tiles of 8 cols ----
        float sf[8][4];
#pragma unroll
        for (int ni = 0; ni < 8; ni++)
#pragma unroll
            for (int r = 0; r < 4; r++) sf[ni][r] = 0.f;

#pragma unroll
        for (int ks = 0; ks < 16; ks++) {
            int k0 = ks * 8;
            uint32_t ah[4], al[4];
            split_tf32(Qs[(r0 + gid) * QS_STRIDE + k0 + t4],          ah[0], al[0]);
            split_tf32(Qs[(r0 + gid + 8) * QS_STRIDE + k0 + t4],      ah[1], al[1]);
            split_tf32(Qs[(r0 + gid) * QS_STRIDE + k0 + t4 + 4],      ah[2], al[2]);
            split_tf32(Qs[(r0 + gid + 8) * QS_STRIDE + k0 + t4 + 4],  ah[3], al[3]);
#pragma unroll
            for (int ni = 0; ni < 8; ni++) {
                uint32_t bh[2], bl[2];
                split_tf32(Ks[(ni * 8 + gid) * KS_STRIDE + k0 + t4],     bh[0], bl[0]);
                split_tf32(Ks[(ni * 8 + gid) * KS_STRIDE + k0 + t4 + 4], bh[1], bl[1]);
                mma_tf32(sf[ni], ah[0], ah[1], ah[2], ah[3], bh[0], bh[1]);
                mma_tf32(sf[ni], ah[0], ah[1], ah[2], ah[3], bl[0], bl[1]);
                mma_tf32(sf[ni], al[0], al[1], al[2], al[3], bh[0], bh[1]);
            }
        }

        // ---- causal mask (only last two tiles) ----
        if (kb >= 2 * qb) {
            int R0 = qb * 128 + r0 + gid;
            int R1 = R0 + 8;
            int jb = kb * 64;
#pragma unroll
            for (int ni = 0; ni < 8; ni++) {
                int c0 = jb + ni * 8 + t4 * 2;
                if (c0     > R0) sf[ni][0] = -1e30f;
                if (c0 + 1 > R0) sf[ni][1] = -1e30f;
                if (c0     > R1) sf[ni][2] = -1e30f;
                if (c0 + 1 > R1) sf[ni][3] = -1e30f;
            }
        }

        // ---- online softmax, per-thread rows gid / gid+8 ----
        float mx0 = -1e30f, mx1 = -1e30f;
#pragma unroll
        for (int ni = 0; ni < 8; ni++) {
            mx0 = fmaxf(mx0, fmaxf(sf[ni][0], sf[ni][1]));
            mx1 = fmaxf(mx1, fmaxf(sf[ni][2], sf[ni][3]));
        }
        mx0 = fmaxf(mx0, __shfl_xor_sync(0xffffffffu, mx0, 1));
        mx0 = fmaxf(mx0, __shfl_xor_sync(0xffffffffu, mx0, 2));
        mx1 = fmaxf(mx1, __shfl_xor_sync(0xffffffffu, mx1, 1));
        mx1 = fmaxf(mx1, __shfl_xor_sync(0xffffffffu, mx1, 2));

        float mn0 = fmaxf(mst0, mx0), mn1 = fmaxf(mst1, mx1);
        float a0 = __expf(mst0 - mn0), a1 = __expf(mst1 - mn1);
        mst0 = mn0; mst1 = mn1;

        float ls0 = 0.f, ls1 = 0.f;
#pragma unroll
        for (int ni = 0; ni < 8; ni++) {
            sf[ni][0] = __expf(sf[ni][0] - mn0);
            sf[ni][1] = __expf(sf[ni][1] - mn0);
            sf[ni][2] = __expf(sf[ni][2] - mn1);
            sf[ni][3] = __expf(sf[ni][3] - mn1);
            ls0 += sf[ni][0] + sf[ni][1];
            ls1 += sf[ni][2] + sf[ni][3];
        }
        ls0 += __shfl_xor_sync(0xffffffffu, ls0, 1);
        ls0 += __shfl_xor_sync(0xffffffffu, ls0, 2);
        ls1 += __shfl_xor_sync(0xffffffffu, ls1, 1);
        ls1 += __shfl_xor_sync(0xffffffffu, ls1, 2);
        lst0 = a0 * lst0 + ls0;
        lst1 = a1 * lst1 + ls1;

        // rescale O
#pragma unroll
        for (int ni = 0; ni < 16; ni++) {
            of[ni][0] *= a0; of[ni][1] *= a0;
            of[ni][2] *= a1; of[ni][3] *= a1;
        }

        // ---- write P to smem (A-layout for PV gemm) ----
#pragma unroll
        for (int ni = 0; ni < 8; ni++) {
            int cc = ni * 8 + t4 * 2;
            Ps[(r0 + gid) * PS_STRIDE + cc]         = sf[ni][0];
            Ps[(r0 + gid) * PS_STRIDE + cc + 1]     = sf[ni][1];
            Ps[(r0 + gid + 8) * PS_STRIDE + cc]     = sf[ni][2];
            Ps[(r0 + gid + 8) * PS_STRIDE + cc + 1] = sf[ni][3];
        }
        __syncthreads();

        // ---- O += P @ V : k = j (64), n = d (128 -> 16 tiles) ----
#pragma unroll
        for (int ks = 0; ks < 8; ks++) {
            int k0 = ks * 8;
            uint32_t ah[4], al[4];
            split_tf32(Ps[(r0 + gid) * PS_STRIDE + k0 + t4],          ah[0], al[0]);
            split_tf32(Ps[(r0 + gid + 8) * PS_STRIDE + k0 + t4],      ah[1], al[1]);
            split_tf32(Ps[(r0 + gid) * PS_STRIDE + k0 + t4 + 4],      ah[2], al[2]);
            split_tf32(Ps[(r0 + gid + 8) * PS_STRIDE + k0 + t4 + 4],  ah[3], al[3]);
#pragma unroll
            for (int ni = 0; ni < 16; ni++) {
                uint32_t bh[2], bl[2];
                split_tf32(Vt[(ni * 8 + gid) * VT_STRIDE + k0 + t4],     bh[0], bl[0]);
                split_tf32(Vt[(ni * 8 + gid) * VT_STRIDE + k0 + t4 + 4], bh[1], bl[1]);
                mma_tf32(of[ni], ah[0], ah[1], ah[2], ah[3], bh[0], bh[1]);
                mma_tf32(of[ni], ah[0], ah[1], ah[2], ah[3], bl[0], bl[1]);
                mma_tf32(of[ni], al[0], al[1], al[2], al[3], bh[0], bh[1]);
            }
        }
    }

    // ---- epilogue ----
    float li0 = 1.0f / lst0, li1 = 1.0f / lst1;
    int R0 = qb * 128 + r0 + gid;
    int R1 = R0 + 8;
#pragma unroll
    for (int ni = 0; ni < 16; ni++) {
        int col = h * HD + ni * 8 + t4 * 2;
        *(float2*)&g_attn[(size_t)R0 * (NH * HD) + col] =
            make_float2(of[ni][0] * li0, of[ni][1] * li0);
        *(float2*)&g_attn[(size_t)R1 * (NH * HD) + col] =
            make_float2(of[ni][2] * li1, of[ni][3] * li1);
    }
}

// ---------------- launch ----------------
extern "C" void kernel_launch(void* const* d_in, const int* in_sizes, int n_in,
                              void* d_out, int out_size)
{
    const int*   positions = (const int*)d_in[0];
    const float* hidden    = (const float*)d_in[1];
    const float* w_qkv     = (const float*)d_in[2];
    const float* w_o       = (const float*)d_in[3];
    const float* qw        = (const float*)d_in[4];
    const float* kw        = (const float*)d_in[5];
    float*       out       = (float*)d_out;

    float *qkvp, *attnp;
    cudaGetSymbolAddress((void**)&qkvp,  g_qkv);
    cudaGetSymbolAddress((void**)&attnp, g_attn);

    cudaFuncSetAttribute(gemm_tf32_async,
                         cudaFuncAttributeMaxDynamicSharedMemorySize, GEMM_SMEM);
    cudaFuncSetAttribute(flash_mma_kernel,
                         cudaFuncAttributeMaxDynamicSharedMemorySize, FLASH_SMEM);

    // 1) QKV projection
    gemm_tf32_async<<<dim3(QKVW / 128, T / 128), 256, GEMM_SMEM>>>(
        hidden, w_qkv, qkvp, T, QKVW, H);

    // 2) LayerNorm + RoPE
    norm_rope_kernel<<<dim3(T, NH + NKV), 128>>>(positions, qw, kw);

    // 3) tensor-core causal flash attention
    flash_mma_kernel<<<dim3(T / 128, NH), 256, FLASH_SMEM>>>();

    // 4) output projection
    gemm_tf32_async<<<dim3(H / 128, T / 128), 256, GEMM_SMEM>>>(
        attnp, w_o, out, T, H, NH * HD);
}

// round 7
// speedup vs baseline: 1.8843x; 1.0637x over previous
#include <cuda_runtime.h>
#include <cuda_bf16.h>
#include <math.h>
#include <stdint.h>

#define T 2048
#define H 4096
#define NH 32
#define NKV 8
#define HD 128
#define QKVW ((NH + 2 * NKV) * HD)   /* 6144 */
#define SCALE 0.08838834764831845f   /* HD^-0.5 */

// ---------------- scratch (static device memory; no allocs allowed) ----------
__device__ float g_qkv[T * QKVW];
__device__ float g_q[T * NH * HD];
__device__ float g_k[T * NKV * HD];
__device__ float g_attn[T * NH * HD];

// ================= bf16x3 mma helpers ================
// fp32 x = hi + lo, hi = truncate-to-bf16(x), lo = x - hi (then bf16-truncated).
// A*B ~= Ah*Bh + Ah*Bl + Al*Bh  (rel err ~2^-16, fp32-class after accumulation).

__device__ __forceinline__ void mma_bf16(float c[4],
    uint32_t a0, uint32_t a1, uint32_t a2, uint32_t a3,
    uint32_t b0, uint32_t b1)
{
    asm volatile(
        "mma.sync.aligned.m16n8k16.row.col.f32.bf16.bf16.f32 "
        "{%0,%1,%2,%3},{%4,%5,%6,%7},{%8,%9},{%0,%1,%2,%3};\n"
        : "+f"(c[0]), "+f"(c[1]), "+f"(c[2]), "+f"(c[3])
        : "r"(a0), "r"(a1), "r"(a2), "r"(a3), "r"(b0), "r"(b1));
}

// pack high 16 bits of two floats: result = {hi16(x1), hi16(x0)} (x0 in low half)
__device__ __forceinline__ uint32_t pack_hi16(float x0, float x1)
{
    uint32_t r;
    asm("prmt.b32 %0, %1, %2, 0x7632;"
        : "=r"(r) : "r"(__float_as_uint(x0)), "r"(__float_as_uint(x1)));
    return r;
}

// split a k-consecutive pair (x0 = even k, x1 = odd k) into bf16x2 hi + lo regs
__device__ __forceinline__ void split2(float x0, float x1, uint32_t& h, uint32_t& l)
{
    h = pack_hi16(x0, x1);
    float l0 = x0 - __uint_as_float(__float_as_uint(x0) & 0xffff0000u);
    float l1 = x1 - __uint_as_float(__float_as_uint(x1) & 0xffff0000u);
    l = pack_hi16(l0, l1);
}

__device__ __forceinline__ void cp_async16(uint32_t dst, const void* src)
{
    asm volatile("cp.async.cg.shared.global [%0], [%1], 16;\n"
                 :: "r"(dst), "l"(src));
}

// ================= bf16x3 GEMM, cp.async 2-stage, BK=32 ================
// C[M,N] = A[M,K] @ B[K,N] row-major. BM=BN=128, 256 threads, warp tile 64x32.
#define AS_STRIDE 40               /* As[m][k]: float2 frag loads conflict-free */
#define BS_STRIDE 132              /* Bs[k][n]: (264t4+g)%32 = 8t4+g -> cf */
#define AS_SIZE (128 * AS_STRIDE)  /* 5120 floats */
#define BS_SIZE (32 * BS_STRIDE)   /* 4224 floats */
#define G_STAGE (AS_SIZE + BS_SIZE)
#define GEMM_SMEM (2 * G_STAGE * 4)   /* 74752 B */

__global__ __launch_bounds__(256, 2) void gemm_bf16x3(
    const float* __restrict__ A, const float* __restrict__ B,
    float* __restrict__ C, int M, int N, int K)
{
    extern __shared__ float smg[];

    int tid  = threadIdx.x;
    int warp = tid >> 5, lane = tid & 31;
    int gid  = lane >> 2, t4 = lane & 3;
    int wm   = (warp >> 2) * 64;
    int wn   = (warp & 3) * 32;
    int bm   = blockIdx.y * 128;
    int bn   = blockIdx.x * 128;

    float acc[4][4][4];
#pragma unroll
    for (int mi = 0; mi < 4; mi++)
#pragma unroll
        for (int ni = 0; ni < 4; ni++)
#pragma unroll
            for (int r = 0; r < 4; r++) acc[mi][ni][r] = 0.f;

    uint32_t smbase = (uint32_t)__cvta_generic_to_shared(smg);
    int ar_base = tid >> 3;          // + 32*i
    int ac      = (tid & 7) * 4;
    int br_base = tid >> 5;          // + 8*i
    int bc      = (tid & 31) * 4;

    int niter = K >> 5;

    // prologue: stage 0
    {
#pragma unroll
        for (int i = 0; i < 4; i++) {
            int ar = ar_base + 32 * i;
            cp_async16(smbase + (ar * AS_STRIDE + ac) * 4,
                       A + (size_t)(bm + ar) * K + ac);
        }
#pragma unroll
        for (int i = 0; i < 4; i++) {
            int br = br_base + 8 * i;
            cp_async16(smbase + (AS_SIZE + br * BS_STRIDE + bc) * 4,
                       B + (size_t)br * N + bn + bc);
        }
        asm volatile("cp.async.commit_group;\n");
    }

    for (int it = 0; it < niter; it++) {
        int s = it & 1;
        if (it + 1 < niter) {
            int kt = (it + 1) << 5;
            uint32_t sb = smbase + (s ^ 1) * G_STAGE * 4;
#pragma unroll
            for (int i = 0; i < 4; i++) {
                int ar = ar_base + 32 * i;
                cp_async16(sb + (ar * AS_STRIDE + ac) * 4,
                           A + (size_t)(bm + ar) * K + kt + ac);
            }
#pragma unroll
            for (int i = 0; i < 4; i++) {
                int br = br_base + 8 * i;
                cp_async16(sb + (AS_SIZE + br * BS_STRIDE + bc) * 4,
                           B + (size_t)(kt + br) * N + bn + bc);
            }
            asm volatile("cp.async.commit_group;\n");
            asm volatile("cp.async.wait_group 1;\n");
        } else {
            asm volatile("cp.async.wait_group 0;\n");
        }
        __syncthreads();

        const float* As = smg + s * G_STAGE;
        const float* Bs = As + AS_SIZE;

#pragma unroll
        for (int kc = 0; kc < 32; kc += 16) {
            uint32_t ah[4][4], al[4][4];
#pragma unroll
            for (int mi = 0; mi < 4; mi++) {
                int m = wm + mi * 16 + gid;
                const float* Ar0 = &As[m * AS_STRIDE + kc + 2 * t4];
                const float* Ar1 = &As[(m + 8) * AS_STRIDE + kc + 2 * t4];
                float2 x0 = *(const float2*)Ar0;         // a0: row m,   k 2t4..+1
                float2 x1 = *(const float2*)Ar1;         // a1: row m+8
                float2 x2 = *(const float2*)(Ar0 + 8);   // a2: row m,   k +8
                float2 x3 = *(const float2*)(Ar1 + 8);   // a3: row m+8, k +8
                split2(x0.x, x0.y, ah[mi][0], al[mi][0]);
                split2(x1.x, x1.y, ah[mi][1], al[mi][1]);
                split2(x2.x, x2.y, ah[mi][2], al[mi][2]);
                split2(x3.x, x3.y, ah[mi][3], al[mi][3]);
            }
#pragma unroll
            for (int ni = 0; ni < 4; ni++) {
                int n = wn + ni * 8 + gid;
                const float* Bp = &Bs[(kc + 2 * t4) * BS_STRIDE + n];
                float b00 = Bp[0];
                float b01 = Bp[BS_STRIDE];
                float b10 = Bp[8 * BS_STRIDE];
                float b11 = Bp[9 * BS_STRIDE];
                uint32_t bh0, bl0, bh1, bl1;
                split2(b00, b01, bh0, bl0);
                split2(b10, b11, bh1, bl1);
#pragma unroll
                for (int mi = 0; mi < 4; mi++) {
                    mma_bf16(acc[mi][ni], ah[mi][0], ah[mi][1], ah[mi][2], ah[mi][3], bh0, bh1);
                    mma_bf16(acc[mi][ni], ah[mi][0], ah[mi][1], ah[mi][2], ah[mi][3], bl0, bl1);
                    mma_bf16(acc[mi][ni], al[mi][0], al[mi][1], al[mi][2], al[mi][3], bh0, bh1);
                }
            }
        }
        __syncthreads();
    }

#pragma unroll
    for (int mi = 0; mi < 4; mi++)
#pragma unroll
        for (int ni = 0; ni < 4; ni++) {
            int row = bm + wm + mi * 16 + gid;
            int col = bn + wn + ni * 8 + t4 * 2;
            *(float2*)&C[(size_t)row * N + col] =
                make_float2(acc[mi][ni][0], acc[mi][ni][1]);
            *(float2*)&C[(size_t)(row + 8) * N + col] =
                make_float2(acc[mi][ni][2], acc[mi][ni][3]);
        }
}

// ---------------- per-(token, head) LayerNorm + interleaved RoPE -------------
__global__ __launch_bounds__(128) void norm_rope_kernel(
    const int* __restrict__ positions,
    const float* __restrict__ qw, const float* __restrict__ kw)
{
    int t  = blockIdx.x;
    int hh = blockIdx.y;
    bool is_q = hh < NH;
    int head  = is_q ? hh : hh - NH;
    int base  = t * QKVW + (is_q ? head * HD : NH * HD + head * HD);
    int c = threadIdx.x;

    float x = g_qkv[base + c];

    __shared__ float red[4];
    __shared__ float ybuf[HD];

    float s = x;
#pragma unroll
    for (int o = 16; o; o >>= 1) s += __shfl_xor_sync(0xffffffffu, s, o);
    if ((c & 31) == 0) red[c >> 5] = s;
    __syncthreads();
    float mean = (red[0] + red[1] + red[2] + red[3]) * (1.0f / HD);
    __syncthreads();

    float d  = x - mean;
    float s2 = d * d;
#pragma unroll
    for (int o = 16; o; o >>= 1) s2 += __shfl_xor_sync(0xffffffffu, s2, o);
    if ((c & 31) == 0) red[c >> 5] = s2;
    __syncthreads();
    float var = (red[0] + red[1] + red[2] + red[3]) * (1.0f / HD);

    float w = is_q ? qw[head * HD + c] : kw[head * HD + c];
    ybuf[c] = d * rsqrtf(var + 1e-5f) * w;
    __syncthreads();

    if (c < HD / 2) {
        float x1 = ybuf[2 * c], x2 = ybuf[2 * c + 1];
        float fpos = (float)positions[t];
        float inv_freq = exp2f(-((float)(2 * c) * (1.0f / HD)) * 13.287712379549449f);
        float f = fpos * inv_freq;
        float sn, cs;
        sincosf(f, &sn, &cs);
        float o1 = x1 * cs - x2 * sn;
        float o2 = x2 * cs + x1 * sn;
        if (is_q) {
            float* dst = &g_q[t * (NH * HD) + head * HD];
            dst[2 * c]     = o1 * SCALE;
            dst[2 * c + 1] = o2 * SCALE;
        } else {
            float* dst = &g_k[t * (NKV * HD) + head * HD];
            dst[2 * c]     = o1;
            dst[2 * c + 1] = o2;
        }
    }
}

// ================= bf16x3 tensor-core flash attention =================
// BM=128, BN=64, 256 thr = 8 warps; warp owns 16 Q rows; softmax in registers.
#define QS_STRIDE 136   /* float2 frag loads: pair idx (4g+t4)%16 cf */
#define KS_STRIDE 136
#define VT_STRIDE 72    /* Vt[d][j]: pair idx (4g+t4)%16 cf */
#define PS_STRIDE 72
#define QS_SZ (128 * QS_STRIDE)
#define KS_SZ (64 * KS_STRIDE)
#define VT_SZ (128 * VT_STRIDE)
#define PS_SZ (128 * PS_STRIDE)
#define FLASH_SMEM ((QS_SZ + KS_SZ + VT_SZ + PS_SZ) * 4)   /* 178176 B */

__global__ __launch_bounds__(256) void flash_mma_kernel()
{
    extern __shared__ float smf[];
    float* Qs = smf;
    float* Ks = Qs + QS_SZ;
    float* Vt = Ks + KS_SZ;
    float* Ps = Vt + VT_SZ;

    int qb  = (gridDim.x - 1) - blockIdx.x;   // heavy blocks first
    int h   = blockIdx.y;
    int hkv = h >> 2;
    int tid = threadIdx.x;
    int w   = tid >> 5, lane = tid & 31;
    int gid = lane >> 2, t4 = lane & 3;
    int r0  = w * 16;

    // ---- load Q tile [128][128] ----
    for (int idx = tid; idx < 128 * 32; idx += 256) {
        int r = idx >> 5, c4 = (idx & 31) << 2;
        float4 v = *(const float4*)&g_q[(qb * 128 + r) * (NH * HD) + h * HD + c4];
        *(float4*)&Qs[r * QS_STRIDE + c4] = v;
    }

    float of[16][4];
#pragma unroll
    for (int ni = 0; ni < 16; ni++)
#pragma unroll
        for (int r = 0; r < 4; r++) of[ni][r] = 0.f;
    float mst0 = -1e30f, mst1 = -1e30f, lst0 = 0.f, lst1 = 0.f;

    int nkb = 2 * qb + 2;
    for (int kb = 0; kb < nkb; kb++) {
        __syncthreads();

        // ---- K tile natural [j][d] ----
        for (int idx = tid; idx < 64 * 32; idx += 256) {
            int j = idx >> 5, c4 = (idx & 31) << 2;
            float4 v = *(const float4*)&g_k[(kb * 64 + j) * (NKV * HD) + hkv * HD + c4];
            *(float4*)&Ks[j * KS_STRIDE + c4] = v;
        }
        // ---- V tile transposed [d][j]; lane-per-row read -> cf smem writes ----
        for (int idx = tid; idx < 64 * 32; idx += 256) {
            int j  = idx & 63;
            int c4 = (idx >> 6) << 2;
            float4 v = *(const float4*)
                &g_qkv[(kb * 64 + j) * QKVW + (NH + NKV) * HD + hkv * HD + c4];
            Vt[(c4 + 0) * VT_STRIDE + j] = v.x;
            Vt[(c4 + 1) * VT_STRIDE + j] = v.y;
            Vt[(c4 + 2) * VT_STRIDE + j] = v.z;
            Vt[(c4 + 3) * VT_STRIDE + j] = v.w;
        }
        __syncthreads();

        // ---- S = Q @ K^T : 8 k16 slabs x 8 n-tiles ----
        float sf[8][4];
#pragma unroll
        for (int ni = 0; ni < 8; ni++)
#pragma unroll
            for (int r = 0; r < 4; r++) sf[ni][r] = 0.f;

#pragma unroll
        for (int ks = 0; ks < 8; ks++) {
            int k0 = ks * 16;
            const float* Qr0 = &Qs[(r0 + gid) * QS_STRIDE + k0 + 2 * t4];
            const float* Qr1 = &Qs[(r0 + gid + 8) * QS_STRIDE + k0 + 2 * t4];
            float2 x0 = *(const float2*)Qr0;
            float2 x1 = *(const float2*)Qr1;
            float2 x2 = *(const float2*)(Qr0 + 8);
            float2 x3 = *(const float2*)(Qr1 + 8);
            uint32_t ah[4], al[4];
            split2(x0.x, x0.y, ah[0], al[0]);
            split2(x1.x, x1.y, ah[1], al[1]);
            split2(x2.x, x2.y, ah[2], al[2]);
            split2(x3.x, x3.y, ah[3], al[3]);
#pragma unroll
            for (int ni = 0; ni < 8; ni++) {
                const float* Kp = &Ks[(ni * 8 + gid) * KS_STRIDE + k0 + 2 * t4];
                float2 y0 = *(const float2*)Kp;
                float2 y1 = *(const float2*)(Kp + 8);
                uint32_t bh0, bl0, bh1, bl1;
                split2(y0.x, y0.y, bh0, bl0);
                split2(y1.x, y1.y, bh1, bl1);
                mma_bf16(sf[ni], ah[0], ah[1], ah[2], ah[3], bh0, bh1);
                mma_bf16(sf[ni], ah[0], ah[1], ah[2], ah[3], bl0, bl1);
                mma_bf16(sf[ni], al[0], al[1], al[2], al[3], bh0, bh1);
            }
        }

        // ---- causal mask (only last two tiles) ----
        if (kb >= 2 * qb) {
            int R0 = qb * 128 + r0 + gid;
            int R1 = R0 + 8;
            int jb = kb * 64;
#pragma unroll
            for (int ni = 0; ni < 8; ni++) {
                int c0 = jb + ni * 8 + t4 * 2;
                if (c0     > R0) sf[ni][0] = -1e30f;
                if (c0 + 1 > R0) sf[ni][1] = -1e30f;
                if (c0     > R1) sf[ni][2] = -1e30f;
                if (c0 + 1 > R1) sf[ni][3] = -1e30f;
            }
        }

        // ---- online softmax ----
        float mx0 = -1e30f, mx1 = -1e30f;
#pragma unroll
        for (int ni = 0; ni < 8; ni++) {
            mx0 = fmaxf(mx0, fmaxf(sf[ni][0], sf[ni][1]));
            mx1 = fmaxf(mx1, fmaxf(sf[ni][2], sf[ni][3]));
        }
        mx0 = fmaxf(mx0, __shfl_xor_sync(0xffffffffu, mx0, 1));
        mx0 = fmaxf(mx0, __shfl_xor_sync(0xffffffffu, mx0, 2));
        mx1 = fmaxf(mx1, __shfl_xor_sync(0xffffffffu, mx1, 1));
        mx1 = fmaxf(mx1, __shfl_xor_sync(0xffffffffu, mx1, 2));

        float mn0 = fmaxf(mst0, mx0), mn1 = fmaxf(mst1, mx1);
        float a0 = __expf(mst0 - mn0), a1 = __expf(mst1 - mn1);
        mst0 = mn0; mst1 = mn1;

        float ls0 = 0.f, ls1 = 0.f;
#pragma unroll
        for (int ni = 0; ni < 8; ni++) {
            sf[ni][0] = __expf(sf[ni][0] - mn0);
            sf[ni][1] = __expf(sf[ni][1] - mn0);
            sf[ni][2] = __expf(sf[ni][2] - mn1);
            sf[ni][3] = __expf(sf[ni][3] - mn1);
            ls0 += sf[ni][0] + sf[ni][1];
            ls1 += sf[ni][2] + sf[ni][3];
        }
        ls0 += __shfl_xor_sync(0xffffffffu, ls0, 1);
        ls0 += __shfl_xor_sync(0xffffffffu, ls0, 2);
        ls1 += __shfl_xor_sync(0xffffffffu, ls1, 1);
        ls1 += __shfl_xor_sync(0xffffffffu, ls1, 2);
        lst0 = a0 * lst0 + ls0;
        lst1 = a1 * lst1 + ls1;

#pragma unroll
        for (int ni = 0; ni < 16; ni++) {
            of[ni][0] *= a0; of[ni][1] *= a0;
            of[ni][2] *= a1; of[ni][3] *= a1;
        }

        // ---- write P (A-layout) ----
#pragma unroll
        for (int ni = 0; ni < 8; ni++) {
            int cc = ni * 8 + t4 * 2;
            *(float2*)&Ps[(r0 + gid) * PS_STRIDE + cc] =
                make_float2(sf[ni][0], sf[ni][1]);
            *(float2*)&Ps[(r0 + gid + 8) * PS_STRIDE + cc] =
                make_float2(sf[ni][2], sf[ni][3]);
        }
        __syncthreads();

        // ---- O += P @ V : 4 k16 slabs x 16 n-tiles ----
#pragma unroll
        for (int ks = 0; ks < 4; ks++) {
            int k0 = ks * 16;
            const float* Pr0 = &Ps[(r0 + gid) * PS_STRIDE + k0 + 2 * t4];
            const float* Pr1 = &Ps[(r0 + gid + 8) * PS_STRIDE + k0 + 2 * t4];
            float2 x0 = *(const float2*)Pr0;
            float2 x1 = *(const float2*)Pr1;
            float2 x2 = *(const float2*)(Pr0 + 8);
            float2 x3 = *(const float2*)(Pr1 + 8);
            uint32_t ah[4], al[4];
            split2(x0.x, x0.y, ah[0], al[0]);
            split2(x1.x, x1.y, ah[1], al[1]);
            split2(x2.x, x2.y, ah[2], al[2]);
            split2(x3.x, x3.y, ah[3], al[3]);
#pragma unroll
            for (int ni = 0; ni < 16; ni++) {
                const float* Vp = &Vt[(ni * 8 + gid) * VT_STRIDE + k0 + 2 * t4];
                float2 y0 = *(const float2*)Vp;
                float2 y1 = *(const float2*)(Vp + 8);
                uint32_t bh0, bl0, bh1, bl1;
                split2(y0.x, y0.y, bh0, bl0);
                split2(y1.x, y1.y, bh1, bl1);
                mma_bf16(of[ni], ah[0], ah[1], ah[2], ah[3], bh0, bh1);
                mma_bf16(of[ni], ah[0], ah[1], ah[2], ah[3], bl0, bl1);
                mma_bf16(of[ni], al[0], al[1], al[2], al[3], bh0, bh1);
            }
        }
    }

    // ---- epilogue ----
    float li0 = 1.0f / lst0, li1 = 1.0f / lst1;
    int R0 = qb * 128 + r0 + gid;
    int R1 = R0 + 8;
#pragma unroll
    for (int ni = 0; ni < 16; ni++) {
        int col = h * HD + ni * 8 + t4 * 2;
        *(float2*)&g_attn[(size_t)R0 * (NH * HD) + col] =
            make_float2(of[ni][0] * li0, of[ni][1] * li0);
        *(float2*)&g_attn[(size_t)R1 * (NH * HD) + col] =
            make_float2(of[ni][2] * li1, of[ni][3] * li1);
    }
}

// ---------------- launch ----------------
extern "C" void kernel_launch(void* const* d_in, const int* in_sizes, int n_in,
                              void* d_out, int out_size)
{
    const int*   positions = (const int*)d_in[0];
    const float* hidden    = (const float*)d_in[1];
    const float* w_qkv     = (const float*)d_in[2];
    const float* w_o       = (const float*)d_in[3];
    const float* qw        = (const float*)d_in[4];
    const float* kw        = (const float*)d_in[5];
    float*       out       = (float*)d_out;

    float *qkvp, *attnp;
    cudaGetSymbolAddress((void**)&qkvp,  g_qkv);
    cudaGetSymbolAddress((void**)&attnp, g_attn);

    cudaFuncSetAttribute(gemm_bf16x3,
                         cudaFuncAttributeMaxDynamicSharedMemorySize, GEMM_SMEM);
    cudaFuncSetAttribute(flash_mma_kernel,
                         cudaFuncAttributeMaxDynamicSharedMemorySize, FLASH_SMEM);

    // 1) QKV projection
    gemm_bf16x3<<<dim3(QKVW / 128, T / 128), 256, GEMM_SMEM>>>(
        hidden, w_qkv, qkvp, T, QKVW, H);

    // 2) LayerNorm + RoPE
    norm_rope_kernel<<<dim3(T, NH + NKV), 128>>>(positions, qw, kw);

    // 3) bf16x3 tensor-core causal flash attention
    flash_mma_kernel<<<dim3(T / 128, NH), 256, FLASH_SMEM>>>();

    // 4) output projection
    gemm_bf16x3<<<dim3(H / 128, T / 128), 256, GEMM_SMEM>>>(
        attnp, w_o, out, T, H, NH * HD);
}

// round 8
// speedup vs baseline: 2.9290x; 1.5545x over previous
#include <cuda_runtime.h>
#include <cuda_bf16.h>
#include <math.h>
#include <stdint.h>

#define T 2048
#define H 4096
#define NH 32
#define NKV 8
#define HD 128
#define QKVW ((NH + 2 * NKV) * HD)   /* 6144 */
#define SCALE 0.08838834764831845f   /* HD^-0.5 */

// ---------------- scratch (static device memory; no allocs allowed) ----------
__device__ float g_qkv[T * QKVW];                                  // fp32 QKV
__device__ __align__(256) __nv_bfloat16 g_ah[T * H],      g_al[T * H];        // A planes (hidden / attn-out)
__device__ __align__(256) __nv_bfloat16 g_bh[H * QKVW],   g_bl[H * QKVW];     // B planes (transposed weights)
__device__ __align__(256) __nv_bfloat16 g_qh[T * NH * HD], g_ql[T * NH * HD]; // Q planes
__device__ __align__(256) __nv_bfloat16 g_kh[T * NKV * HD], g_kl[T * NKV * HD];
__device__ __align__(256) __nv_bfloat16 g_vth[NKV * HD * T], g_vtl[NKV * HD * T]; // V^T planes [hkv][d][t]

// ================= helpers ================
__device__ __forceinline__ void mma_bf16(float c[4],
    uint32_t a0, uint32_t a1, uint32_t a2, uint32_t a3,
    uint32_t b0, uint32_t b1)
{
    asm volatile(
        "mma.sync.aligned.m16n8k16.row.col.f32.bf16.bf16.f32 "
        "{%0,%1,%2,%3},{%4,%5,%6,%7},{%8,%9},{%0,%1,%2,%3};\n"
        : "+f"(c[0]), "+f"(c[1]), "+f"(c[2]), "+f"(c[3])
        : "r"(a0), "r"(a1), "r"(a2), "r"(a3), "r"(b0), "r"(b1));
}

// pack high 16 bits of two floats: {hi16(x1), hi16(x0)} (x0 low)
__device__ __forceinline__ uint32_t pack_hi16(float x0, float x1)
{
    uint32_t r;
    asm("prmt.b32 %0, %1, %2, 0x7632;"
        : "=r"(r) : "r"(__float_as_uint(x0)), "r"(__float_as_uint(x1)));
    return r;
}

__device__ __forceinline__ void split2(float x0, float x1, uint32_t& h, uint32_t& l)
{
    h = pack_hi16(x0, x1);
    float l0 = x0 - __uint_as_float(__float_as_uint(x0) & 0xffff0000u);
    float l1 = x1 - __uint_as_float(__float_as_uint(x1) & 0xffff0000u);
    l = pack_hi16(l0, l1);
}

__device__ __forceinline__ void split1(float v, uint16_t& h16, uint16_t& l16)
{
    uint32_t u = __float_as_uint(v);
    h16 = (uint16_t)(u >> 16);
    float lo = v - __uint_as_float(u & 0xffff0000u);
    l16 = (uint16_t)(__float_as_uint(lo) >> 16);
}

__device__ __forceinline__ void cp_async16(uint32_t dst, const void* src)
{
    asm volatile("cp.async.cg.shared.global [%0], [%1], 16;\n"
                 :: "r"(dst), "l"(src));
}

// ================= prep kernels ================
// elementwise split: fp32 -> bf16 hi/lo planes (same layout)
__global__ void split_plane(const float2* __restrict__ in,
    uint32_t* __restrict__ hi, uint32_t* __restrict__ lo, int npairs)
{
    for (int i = blockIdx.x * blockDim.x + threadIdx.x; i < npairs;
         i += gridDim.x * blockDim.x) {
        float2 v = in[i];
        uint32_t h, l;
        split2(v.x, v.y, h, l);
        hi[i] = h; lo[i] = l;
    }
}

// B[K][N] fp32 -> Bt hi/lo bf16 [N][K]
__global__ void split_transpose(const float* __restrict__ B,
    __nv_bfloat16* __restrict__ Bth, __nv_bfloat16* __restrict__ Btl,
    int K, int N)
{
    __shared__ float tile[32][33];
    int n0 = blockIdx.x * 32, k0 = blockIdx.y * 32;
    int tx = threadIdx.x, ty = threadIdx.y;
#pragma unroll
    for (int i = 0; i < 4; i++)
        tile[ty + 8 * i][tx] = B[(size_t)(k0 + ty + 8 * i) * N + n0 + tx];
    __syncthreads();
#pragma unroll
    for (int i = 0; i < 4; i++) {
        float v = tile[tx][ty + 8 * i];
        uint16_t h16, l16;
        split1(v, h16, l16);
        size_t o = (size_t)(n0 + ty + 8 * i) * K + k0 + tx;
        ((uint16_t*)Bth)[o] = h16;
        ((uint16_t*)Btl)[o] = l16;
    }
}

// V region of g_qkv [T][...] -> V^T hi/lo bf16 [hkv][d][t]
__global__ void split_transpose_v()
{
    __shared__ float tile[32][33];
    int t0 = blockIdx.x * 32, d0 = blockIdx.y * 32, hkv = blockIdx.z;
    int tx = threadIdx.x, ty = threadIdx.y;
#pragma unroll
    for (int i = 0; i < 4; i++)
        tile[ty + 8 * i][tx] =
            g_qkv[(size_t)(t0 + ty + 8 * i) * QKVW + (NH + NKV) * HD + hkv * HD + d0 + tx];
    __syncthreads();
#pragma unroll
    for (int i = 0; i < 4; i++) {
        float v = tile[tx][ty + 8 * i];
        uint16_t h16, l16;
        split1(v, h16, l16);
        size_t o = (size_t)hkv * HD * T + (size_t)(d0 + ty + 8 * i) * T + t0 + tx;
        ((uint16_t*)g_vth)[o] = h16;
        ((uint16_t*)g_vtl)[o] = l16;
    }
}

// ================= plane GEMM: pure HMMA mainloop ================
// C[M,N] = A[M,K] @ B[K,N]; A planes [M][K], Bt planes [N][K], all bf16.
// BM=BN=128, BK=32, 256 threads, warp tile 64x32, cp.async 2-stage.
#define PSTRIDE 20                    /* uint32 pairs per row: 16 data + 4 pad */
#define TILE_U32 (128 * PSTRIDE)      /* 2560 */
#define STAGE_U32 (4 * TILE_U32)      /* AsH AsL BsH BsL */
#define GEMM_SMEM (2 * STAGE_U32 * 4) /* 81920 B */

__global__ __launch_bounds__(256, 2) void gemm_planes(
    const __nv_bfloat16* __restrict__ Ah, const __nv_bfloat16* __restrict__ Al,
    const __nv_bfloat16* __restrict__ Bh, const __nv_bfloat16* __restrict__ Bl,
    float* __restrict__ C, int M, int N, int K)
{
    extern __shared__ uint32_t smu[];
    int tid  = threadIdx.x;
    int warp = tid >> 5, lane = tid & 31;
    int gid  = lane >> 2, t4 = lane & 3;
    int wm   = (warp >> 2) * 64;
    int wn   = (warp & 3) * 32;
    int bm   = blockIdx.y * 128;
    int bn   = blockIdx.x * 128;

    float acc[4][4][4];
#pragma unroll
    for (int mi = 0; mi < 4; mi++)
#pragma unroll
        for (int ni = 0; ni < 4; ni++)
#pragma unroll
            for (int r = 0; r < 4; r++) acc[mi][ni][r] = 0.f;

    uint32_t smbase = (uint32_t)__cvta_generic_to_shared(smu);
    int lr = tid >> 2;     // 0..63
    int lc = tid & 3;      // 16B chunk within 64B row

    auto load_stage = [&](int s, int kt) {
        uint32_t base = smbase + s * STAGE_U32 * 4;
#pragma unroll
        for (int half = 0; half < 2; half++) {
            int r = lr + 64 * half;
            uint32_t d = base + (r * PSTRIDE + lc * 4) * 4;
            cp_async16(d,                    Ah + (size_t)(bm + r) * K + kt + lc * 8);
            cp_async16(d + TILE_U32 * 4,     Al + (size_t)(bm + r) * K + kt + lc * 8);
            cp_async16(d + 2 * TILE_U32 * 4, Bh + (size_t)(bn + r) * K + kt + lc * 8);
            cp_async16(d + 3 * TILE_U32 * 4, Bl + (size_t)(bn + r) * K + kt + lc * 8);
        }
        asm volatile("cp.async.commit_group;\n");
    };

    load_stage(0, 0);
    int niter = K >> 5;

    for (int it = 0; it < niter; it++) {
        int s = it & 1;
        if (it + 1 < niter) {
            load_stage(s ^ 1, (it + 1) << 5);
            asm volatile("cp.async.wait_group 1;\n");
        } else {
            asm volatile("cp.async.wait_group 0;\n");
        }
        __syncthreads();

        const uint32_t* AsH = smu + s * STAGE_U32;
        const uint32_t* AsL = AsH + TILE_U32;
        const uint32_t* BsH = AsH + 2 * TILE_U32;
        const uint32_t* BsL = AsH + 3 * TILE_U32;

#pragma unroll
        for (int kp0 = 0; kp0 < 16; kp0 += 8) {
            uint32_t bhf[4][2], blf[4][2];
#pragma unroll
            for (int ni = 0; ni < 4; ni++) {
                int n = wn + ni * 8 + gid;
                bhf[ni][0] = BsH[n * PSTRIDE + kp0 + t4];
                bhf[ni][1] = BsH[n * PSTRIDE + kp0 + 4 + t4];
                blf[ni][0] = BsL[n * PSTRIDE + kp0 + t4];
                blf[ni][1] = BsL[n * PSTRIDE + kp0 + 4 + t4];
            }
#pragma unroll
            for (int mi = 0; mi < 4; mi++) {
                int m = wm + mi * 16 + gid;
                uint32_t a0 = AsH[m * PSTRIDE + kp0 + t4];
                uint32_t a1 = AsH[(m + 8) * PSTRIDE + kp0 + t4];
                uint32_t a2 = AsH[m * PSTRIDE + kp0 + 4 + t4];
                uint32_t a3 = AsH[(m + 8) * PSTRIDE + kp0 + 4 + t4];
                uint32_t e0 = AsL[m * PSTRIDE + kp0 + t4];
                uint32_t e1 = AsL[(m + 8) * PSTRIDE + kp0 + t4];
                uint32_t e2 = AsL[m * PSTRIDE + kp0 + 4 + t4];
                uint32_t e3 = AsL[(m + 8) * PSTRIDE + kp0 + 4 + t4];
#pragma unroll
                for (int ni = 0; ni < 4; ni++) {
                    mma_bf16(acc[mi][ni], a0, a1, a2, a3, bhf[ni][0], bhf[ni][1]);
                    mma_bf16(acc[mi][ni], a0, a1, a2, a3, blf[ni][0], blf[ni][1]);
                    mma_bf16(acc[mi][ni], e0, e1, e2, e3, bhf[ni][0], bhf[ni][1]);
                }
            }
        }
        __syncthreads();
    }

#pragma unroll
    for (int mi = 0; mi < 4; mi++)
#pragma unroll
        for (int ni = 0; ni < 4; ni++) {
            int row = bm + wm + mi * 16 + gid;
            int col = bn + wn + ni * 8 + t4 * 2;
            *(float2*)&C[(size_t)row * N + col] =
                make_float2(acc[mi][ni][0], acc[mi][ni][1]);
            *(float2*)&C[(size_t)(row + 8) * N + col] =
                make_float2(acc[mi][ni][2], acc[mi][ni][3]);
        }
}

// ---------------- LayerNorm + interleaved RoPE -> Q/K bf16 planes ------------
__global__ __launch_bounds__(128) void norm_rope_kernel(
    const int* __restrict__ positions,
    const float* __restrict__ qw, const float* __restrict__ kw)
{
    int t  = blockIdx.x;
    int hh = blockIdx.y;
    bool is_q = hh < NH;
    int head  = is_q ? hh : hh - NH;
    int base  = t * QKVW + (is_q ? head * HD : NH * HD + head * HD);
    int c = threadIdx.x;

    float x = g_qkv[base + c];

    __shared__ float red[4];
    __shared__ float ybuf[HD];

    float s = x;
#pragma unroll
    for (int o = 16; o; o >>= 1) s += __shfl_xor_sync(0xffffffffu, s, o);
    if ((c & 31) == 0) red[c >> 5] = s;
    __syncthreads();
    float mean = (red[0] + red[1] + red[2] + red[3]) * (1.0f / HD);
    __syncthreads();

    float d  = x - mean;
    float s2 = d * d;
#pragma unroll
    for (int o = 16; o; o >>= 1) s2 += __shfl_xor_sync(0xffffffffu, s2, o);
    if ((c & 31) == 0) red[c >> 5] = s2;
    __syncthreads();
    float var = (red[0] + red[1] + red[2] + red[3]) * (1.0f / HD);

    float w = is_q ? qw[head * HD + c] : kw[head * HD + c];
    ybuf[c] = d * rsqrtf(var + 1e-5f) * w;
    __syncthreads();

    if (c < HD / 2) {
        float x1 = ybuf[2 * c], x2 = ybuf[2 * c + 1];
        float fpos = (float)positions[t];
        float inv_freq = exp2f(-((float)(2 * c) * (1.0f / HD)) * 13.287712379549449f);
        float f = fpos * inv_freq;
        float sn, cs;
        sincosf(f, &sn, &cs);
        float o1 = x1 * cs - x2 * sn;
        float o2 = x2 * cs + x1 * sn;
        uint32_t hh32, ll32;
        if (is_q) {
            split2(o1 * SCALE, o2 * SCALE, hh32, ll32);
            ((uint32_t*)g_qh)[(size_t)t * 2048 + head * 64 + c] = hh32;
            ((uint32_t*)g_ql)[(size_t)t * 2048 + head * 64 + c] = ll32;
        } else {
            split2(o1, o2, hh32, ll32);
            ((uint32_t*)g_kh)[(size_t)t * 512 + head * 64 + c] = hh32;
            ((uint32_t*)g_kl)[(size_t)t * 512 + head * 64 + c] = ll32;
        }
    }
}

// ================= flash attention: pure HMMA mainloop =================
// BM=128, BN=64, 256 thr = 8 warps; warp owns 16 Q rows; state in registers.
// smem all bf16-pair (uint32) planes.
#define QP 68    /* Q/K pair stride: 64 data + 4 pad */
#define VP 36    /* V^T/P pair stride: 32 data + 4 pad */
#define FLASH_SMEM ((2 * 128 * QP + 2 * 64 * QP + 2 * 128 * VP + 2 * 128 * VP) * 4)

__global__ __launch_bounds__(256) void flash_mma_kernel()
{
    extern __shared__ uint32_t smu[];
    uint32_t* QH = smu;
    uint32_t* QL = QH + 128 * QP;
    uint32_t* KH = QL + 128 * QP;
    uint32_t* KL = KH + 64 * QP;
    uint32_t* VH = KL + 64 * QP;
    uint32_t* VL = VH + 128 * VP;
    uint32_t* PH = VL + 128 * VP;
    uint32_t* PL = PH + 128 * VP;

    int qb  = (gridDim.x - 1) - blockIdx.x;   // heavy blocks first
    int h   = blockIdx.y;
    int hkv = h >> 2;
    int tid = threadIdx.x;
    int w   = tid >> 5, lane = tid & 31;
    int gid = lane >> 2, t4 = lane & 3;
    int r0  = w * 16;

    // ---- load Q planes [128 rows][64 pairs] ----
    {
        const uint4* qh4 = (const uint4*)g_qh + ((size_t)(qb * 128) * (NH * HD) + h * HD) / 8;
        const uint4* ql4 = (const uint4*)g_ql + ((size_t)(qb * 128) * (NH * HD) + h * HD) / 8;
        for (int idx = tid; idx < 128 * 16; idx += 256) {
            int r = idx >> 4, u = idx & 15;
            *(uint4*)&QH[r * QP + u * 4] = qh4[r * 512 + u];
            *(uint4*)&QL[r * QP + u * 4] = ql4[r * 512 + u];
        }
    }

    float of[16][4];
#pragma unroll
    for (int ni = 0; ni < 16; ni++)
#pragma unroll
        for (int r = 0; r < 4; r++) of[ni][r] = 0.f;
    float mst0 = -1e30f, mst1 = -1e30f, lst0 = 0.f, lst1 = 0.f;

    int nkb = 2 * qb + 2;
    for (int kb = 0; kb < nkb; kb++) {
        __syncthreads();

        // ---- K planes [64 rows][64 pairs] ----
        {
            const uint4* kh4 = (const uint4*)g_kh + ((size_t)(kb * 64) * (NKV * HD) + hkv * HD) / 8;
            const uint4* kl4 = (const uint4*)g_kl + ((size_t)(kb * 64) * (NKV * HD) + hkv * HD) / 8;
            for (int idx = tid; idx < 64 * 16; idx += 256) {
                int r = idx >> 4, u = idx & 15;
                *(uint4*)&KH[r * QP + u * 4] = kh4[r * 128 + u];
                *(uint4*)&KL[r * QP + u * 4] = kl4[r * 128 + u];
            }
        }
        // ---- V^T planes [128 d][32 pairs] (pre-transposed in gmem) ----
        {
            const uint4* vh4 = (const uint4*)g_vth + ((size_t)hkv * HD * T + (size_t)kb * 64) / 8;
            const uint4* vl4 = (const uint4*)g_vtl + ((size_t)hkv * HD * T + (size_t)kb * 64) / 8;
            for (int idx = tid; idx < 128 * 8; idx += 256) {
                int d = idx >> 3, u = idx & 7;
                *(uint4*)&VH[d * VP + u * 4] = vh4[d * 256 + u];
                *(uint4*)&VL[d * VP + u * 4] = vl4[d * 256 + u];
            }
        }
        __syncthreads();

        // ---- S = Q @ K^T : 8 k16 slabs x 8 n-tiles, pure LDS+MMA ----
        float sf[8][4];
#pragma unroll
        for (int ni = 0; ni < 8; ni++)
#pragma unroll
            for (int r = 0; r < 4; r++) sf[ni][r] = 0.f;

#pragma unroll
        for (int ks = 0; ks < 8; ks++) {
            int kp = ks * 8;
            uint32_t a0 = QH[(r0 + gid) * QP + kp + t4];
            uint32_t a1 = QH[(r0 + gid + 8) * QP + kp + t4];
            uint32_t a2 = QH[(r0 + gid) * QP + kp + 4 + t4];
            uint32_t a3 = QH[(r0 + gid + 8) * QP + kp + 4 + t4];
            uint32_t e0 = QL[(r0 + gid) * QP + kp + t4];
            uint32_t e1 = QL[(r0 + gid + 8) * QP + kp + t4];
            uint32_t e2 = QL[(r0 + gid) * QP + kp + 4 + t4];
            uint32_t e3 = QL[(r0 + gid + 8) * QP + kp + 4 + t4];
#pragma unroll
            for (int ni = 0; ni < 8; ni++) {
                int n = ni * 8 + gid;
                uint32_t b0 = KH[n * QP + kp + t4];
                uint32_t b1 = KH[n * QP + kp + 4 + t4];
                uint32_t f0 = KL[n * QP + kp + t4];
                uint32_t f1 = KL[n * QP + kp + 4 + t4];
                mma_bf16(sf[ni], a0, a1, a2, a3, b0, b1);
                mma_bf16(sf[ni], a0, a1, a2, a3, f0, f1);
                mma_bf16(sf[ni], e0, e1, e2, e3, b0, b1);
            }
        }

        // ---- causal mask ----
        if (kb >= 2 * qb) {
            int R0 = qb * 128 + r0 + gid;
            int R1 = R0 + 8;
            int jb = kb * 64;
#pragma unroll
            for (int ni = 0; ni < 8; ni++) {
                int c0 = jb + ni * 8 + t4 * 2;
                if (c0     > R0) sf[ni][0] = -1e30f;
                if (c0 + 1 > R0) sf[ni][1] = -1e30f;
                if (c0     > R1) sf[ni][2] = -1e30f;
                if (c0 + 1 > R1) sf[ni][3] = -1e30f;
            }
        }

        // ---- online softmax ----
        float mx0 = -1e30f, mx1 = -1e30f;
#pragma unroll
        for (int ni = 0; ni < 8; ni++) {
            mx0 = fmaxf(mx0, fmaxf(sf[ni][0], sf[ni][1]));
            mx1 = fmaxf(mx1, fmaxf(sf[ni][2], sf[ni][3]));
        }
        mx0 = fmaxf(mx0, __shfl_xor_sync(0xffffffffu, mx0, 1));
        mx0 = fmaxf(mx0, __shfl_xor_sync(0xffffffffu, mx0, 2));
        mx1 = fmaxf(mx1, __shfl_xor_sync(0xffffffffu, mx1, 1));
        mx1 = fmaxf(mx1, __shfl_xor_sync(0xffffffffu, mx1, 2));

        float mn0 = fmaxf(mst0, mx0), mn1 = fmaxf(mst1, mx1);
        float a0 = __expf(mst0 - mn0), a1 = __expf(mst1 - mn1);
        mst0 = mn0; mst1 = mn1;

        float ls0 = 0.f, ls1 = 0.f;
#pragma unroll
        for (int ni = 0; ni < 8; ni++) {
            sf[ni][0] = __expf(sf[ni][0] - mn0);
            sf[ni][1] = __expf(sf[ni][1] - mn0);
            sf[ni][2] = __expf(sf[ni][2] - mn1);
            sf[ni][3] = __expf(sf[ni][3] - mn1);
            ls0 += sf[ni][0] + sf[ni][1];
            ls1 += sf[ni][2] + sf[ni][3];
        }
        ls0 += __shfl_xor_sync(0xffffffffu, ls0, 1);
        ls0 += __shfl_xor_sync(0xffffffffu, ls0, 2);
        ls1 += __shfl_xor_sync(0xffffffffu, ls1, 1);
        ls1 += __shfl_xor_sync(0xffffffffu, ls1, 2);
        lst0 = a0 * lst0 + ls0;
        lst1 = a1 * lst1 + ls1;

#pragma unroll
        for (int ni = 0; ni < 16; ni++) {
            of[ni][0] *= a0; of[ni][1] *= a0;
            of[ni][2] *= a1; of[ni][3] *= a1;
        }

        // ---- write P hi/lo planes (split once per value) ----
#pragma unroll
        for (int ni = 0; ni < 8; ni++) {
            uint32_t ph, pl;
            split2(sf[ni][0], sf[ni][1], ph, pl);
            PH[(r0 + gid) * VP + ni * 4 + t4] = ph;
            PL[(r0 + gid) * VP + ni * 4 + t4] = pl;
            split2(sf[ni][2], sf[ni][3], ph, pl);
            PH[(r0 + gid + 8) * VP + ni * 4 + t4] = ph;
            PL[(r0 + gid + 8) * VP + ni * 4 + t4] = pl;
        }
        __syncthreads();

        // ---- O += P @ V : 4 k16 slabs x 16 n-tiles, pure LDS+MMA ----
#pragma unroll
        for (int ks = 0; ks < 4; ks++) {
            int kp = ks * 8;
            uint32_t a0 = PH[(r0 + gid) * VP + kp + t4];
            uint32_t a1 = PH[(r0 + gid + 8) * VP + kp + t4];
            uint32_t a2 = PH[(r0 + gid) * VP + kp + 4 + t4];
            uint32_t a3 = PH[(r0 + gid + 8) * VP + kp + 4 + t4];
            uint32_t e0 = PL[(r0 + gid) * VP + kp + t4];
            uint32_t e1 = PL[(r0 + gid + 8) * VP + kp + t4];
            uint32_t e2 = PL[(r0 + gid) * VP + kp + 4 + t4];
            uint32_t e3 = PL[(r0 + gid + 8) * VP + kp + 4 + t4];
#pragma unroll
            for (int ni = 0; ni < 16; ni++) {
                int n = ni * 8 + gid;
                uint32_t b0 = VH[n * VP + kp + t4];
                uint32_t b1 = VH[n * VP + kp + 4 + t4];
                uint32_t f0 = VL[n * VP + kp + t4];
                uint32_t f1 = VL[n * VP + kp + 4 + t4];
                mma_bf16(of[ni], a0, a1, a2, a3, b0, b1);
                mma_bf16(of[ni], a0, a1, a2, a3, f0, f1);
                mma_bf16(of[ni], e0, e1, e2, e3, b0, b1);
            }
        }
    }

    // ---- epilogue: write attn output directly as A hi/lo planes ----
    float li0 = 1.0f / lst0, li1 = 1.0f / lst1;
    int R0 = qb * 128 + r0 + gid;
    int R1 = R0 + 8;
    uint32_t* pah = (uint32_t*)g_ah;
    uint32_t* pal = (uint32_t*)g_al;
#pragma unroll
    for (int ni = 0; ni < 16; ni++) {
        int colp = h * 64 + ni * 4 + t4;
        uint32_t hh32, ll32;
        split2(of[ni][0] * li0, of[ni][1] * li0, hh32, ll32);
        pah[(size_t)R0 * 2048 + colp] = hh32;
        pal[(size_t)R0 * 2048 + colp] = ll32;
        split2(of[ni][2] * li1, of[ni][3] * li1, hh32, ll32);
        pah[(size_t)R1 * 2048 + colp] = hh32;
        pal[(size_t)R1 * 2048 + colp] = ll32;
    }
}

// ---------------- launch ----------------
extern "C" void kernel_launch(void* const* d_in, const int* in_sizes, int n_in,
                              void* d_out, int out_size)
{
    const int*   positions = (const int*)d_in[0];
    const float* hidden    = (const float*)d_in[1];
    const float* w_qkv     = (const float*)d_in[2];
    const float* w_o       = (const float*)d_in[3];
    const float* qw        = (const float*)d_in[4];
    const float* kw        = (const float*)d_in[5];
    float*       out       = (float*)d_out;

    float* qkvp;
    __nv_bfloat16 *ahp, *alp, *bhp, *blp;
    cudaGetSymbolAddress((void**)&qkvp, g_qkv);
    cudaGetSymbolAddress((void**)&ahp, g_ah);
    cudaGetSymbolAddress((void**)&alp, g_al);
    cudaGetSymbolAddress((void**)&bhp, g_bh);
    cudaGetSymbolAddress((void**)&blp, g_bl);

    cudaFuncSetAttribute(gemm_planes,
                         cudaFuncAttributeMaxDynamicSharedMemorySize, GEMM_SMEM);
    cudaFuncSetAttribute(flash_mma_kernel,
                         cudaFuncAttributeMaxDynamicSharedMemorySize, FLASH_SMEM);

    // 1) split hidden -> A planes; split+transpose w_qkv -> B planes
    split_plane<<<4096, 256>>>((const float2*)hidden,
                               (uint32_t*)ahp, (uint32_t*)alp, T * H / 2);
    split_transpose<<<dim3(QKVW / 32, H / 32), dim3(32, 8)>>>(w_qkv, bhp, blp, H, QKVW);

    // 2) QKV projection (pure bf16x3 HMMA)
    gemm_planes<<<dim3(QKVW / 128, T / 128), 256, GEMM_SMEM>>>(
        ahp, alp, bhp, blp, qkvp, T, QKVW, H);

    // 3) LayerNorm + RoPE -> Q/K planes; V -> transposed planes
    norm_rope_kernel<<<dim3(T, NH + NKV), 128>>>(positions, qw, kw);
    split_transpose_v<<<dim3(T / 32, HD / 32, NKV), dim3(32, 8)>>>();

    // 4) flash attention -> writes A planes directly
    flash_mma_kernel<<<dim3(T / 128, NH), 256, FLASH_SMEM>>>();

    // 5) split+transpose w_o -> B planes; output projection
    split_transpose<<<dim3(H / 32, (NH * HD) / 32), dim3(32, 8)>>>(w_o, bhp, blp, NH * HD, H);
    gemm_planes<<<dim3(H / 128, T / 128), 256, GEMM_SMEM>>>(
        ahp, alp, bhp, blp, out, T, H, NH * HD);
}